// round 1
// baseline (speedup 1.0000x reference)
#include <cuda_runtime.h>
#include <math.h>

#define NB 4
#define NH 16
#define NS 1024
#define ND 64
#define NE 1024

// Scratch for projected Q/K/V in [B, H, S, 64] layout (16.8 MB each).
__device__ float g_Q[NB*NH*NS*ND];
__device__ float g_K[NB*NH*NS*ND];
__device__ float g_V[NB*NH*NS*ND];

// ---------------------------------------------------------------------------
// Projection GEMM: out[(b,h,s,d)] = (sum_k X[m,k]*W[n,k] + bias[n]) * scale
// X: [4096, 1024] row-major, W: [1024, 1024] row-major (torch Linear weight).
// 128x128 block tile, BK=8, 256 threads, 8x8 microtile (split 4+4 register
// tiles 64 apart so all shared loads are 16B-lane-stride conflict-free).
// ---------------------------------------------------------------------------
__global__ __launch_bounds__(256) void proj128(
    const float* __restrict__ X, const float* __restrict__ W,
    const float* __restrict__ bias, float* __restrict__ out, float scale)
{
    __shared__ float AsT[8][128];   // [k][m]
    __shared__ float BsT[8][128];   // [k][n]
    const int tid = threadIdx.x;
    const int ty = tid >> 4, tx = tid & 15;
    const int m0 = blockIdx.y * 128;
    const int n0 = blockIdx.x * 128;
    const int lrow = tid >> 1;           // 0..127
    const int lk4  = (tid & 1) << 2;     // 0 or 4

    float acc[8][8];
    #pragma unroll
    for (int i = 0; i < 8; i++)
        #pragma unroll
        for (int j = 0; j < 8; j++) acc[i][j] = 0.f;

    for (int k0 = 0; k0 < NE; k0 += 8) {
        float4 a  = *(const float4*)(X + (size_t)(m0 + lrow) * NE + k0 + lk4);
        float4 bw = *(const float4*)(W + (size_t)(n0 + lrow) * NE + k0 + lk4);
        __syncthreads();
        AsT[lk4+0][lrow] = a.x;  AsT[lk4+1][lrow] = a.y;
        AsT[lk4+2][lrow] = a.z;  AsT[lk4+3][lrow] = a.w;
        BsT[lk4+0][lrow] = bw.x; BsT[lk4+1][lrow] = bw.y;
        BsT[lk4+2][lrow] = bw.z; BsT[lk4+3][lrow] = bw.w;
        __syncthreads();
        #pragma unroll
        for (int kk = 0; kk < 8; kk++) {
            float4 a0 = *(const float4*)&AsT[kk][ty*4];
            float4 a1 = *(const float4*)&AsT[kk][64 + ty*4];
            float4 b0 = *(const float4*)&BsT[kk][tx*4];
            float4 b1 = *(const float4*)&BsT[kk][64 + tx*4];
            float aa[8] = {a0.x,a0.y,a0.z,a0.w, a1.x,a1.y,a1.z,a1.w};
            float bb[8] = {b0.x,b0.y,b0.z,b0.w, b1.x,b1.y,b1.z,b1.w};
            #pragma unroll
            for (int i = 0; i < 8; i++)
                #pragma unroll
                for (int j = 0; j < 8; j++)
                    acc[i][j] = fmaf(aa[i], bb[j], acc[i][j]);
        }
    }

    // Epilogue: add bias, scale, permute to [B,H,S,64].
    #pragma unroll
    for (int ig = 0; ig < 2; ig++) {
        #pragma unroll
        for (int i = 0; i < 4; i++) {
            const int m = m0 + ig*64 + ty*4 + i;
            const int b = m >> 10;
            const int s = m & (NS - 1);
            #pragma unroll
            for (int jg = 0; jg < 2; jg++) {
                const int n  = n0 + jg*64 + tx*4;
                const int hh = n >> 6;
                const int dd = n & 63;
                float4 v;
                v.x = (acc[ig*4+i][jg*4+0] + bias[n+0]) * scale;
                v.y = (acc[ig*4+i][jg*4+1] + bias[n+1]) * scale;
                v.z = (acc[ig*4+i][jg*4+2] + bias[n+2]) * scale;
                v.w = (acc[ig*4+i][jg*4+3] + bias[n+3]) * scale;
                *(float4*)(out + ((size_t)((b*NH + hh)*NS + s))*ND + dd) = v;
            }
        }
    }
}

// ---------------------------------------------------------------------------
// Fused flash-style attention. One CTA = (b, h, 64-query tile), 256 threads
// as 16x16, each thread owns a 4x4 score/output microtile. Streams 64-key
// chunks with online softmax; mask read straight from global (once total).
// Dynamic smem: QsT | KsT | Vs | Ps = 4 * 16 KB = 64 KB.
// ---------------------------------------------------------------------------
__global__ __launch_bounds__(256) void attn_kernel(const float* __restrict__ mask,
                                                   float* __restrict__ out)
{
    extern __shared__ float smf[];
    float* QsT = smf;               // [kk][r]  kk*64 + r
    float* KsT = smf + 4096;        // [kk][c]
    float* Vs  = smf + 8192;        // [c][d]
    float* Ps  = smf + 12288;       // [r][c]

    const int b  = blockIdx.z, h = blockIdx.y;
    const int q0 = blockIdx.x * 64;
    const int tid = threadIdx.x;
    const int ty = tid >> 4, tx = tid & 15;
    const int lrow = tid >> 2;           // 0..63
    const int lk4  = (tid & 3) << 2;     // 0,4,8,12

    const size_t base = (size_t)((b*NH + h)*NS) * ND;
    const float* Qg = g_Q + base;
    const float* Kg = g_K + base;
    const float* Vg = g_V + base;

    // Load Q tile transposed: QsT[d][r]
    #pragma unroll
    for (int rep = 0; rep < 4; rep++) {
        const int c = lk4 + rep*16;
        float4 a = *(const float4*)(Qg + (q0 + lrow)*ND + c);
        QsT[(c+0)*64 + lrow] = a.x; QsT[(c+1)*64 + lrow] = a.y;
        QsT[(c+2)*64 + lrow] = a.z; QsT[(c+3)*64 + lrow] = a.w;
    }

    float o[4][4];
    #pragma unroll
    for (int i = 0; i < 4; i++)
        #pragma unroll
        for (int j = 0; j < 4; j++) o[i][j] = 0.f;
    float mrow[4] = {-3.4e38f, -3.4e38f, -3.4e38f, -3.4e38f};
    float lsum[4] = {0.f, 0.f, 0.f, 0.f};

    for (int jt = 0; jt < NS/64; jt++) {
        const int j0 = jt * 64;
        __syncthreads();   // prev iter's PV reads (Ps, Vs) + score reads (KsT) done
        #pragma unroll
        for (int rep = 0; rep < 4; rep++) {
            const int c = lk4 + rep*16;
            float4 kv = *(const float4*)(Kg + (j0 + lrow)*ND + c);
            KsT[(c+0)*64 + lrow] = kv.x; KsT[(c+1)*64 + lrow] = kv.y;
            KsT[(c+2)*64 + lrow] = kv.z; KsT[(c+3)*64 + lrow] = kv.w;
            *(float4*)(Vs + lrow*64 + c) = *(const float4*)(Vg + (j0 + lrow)*ND + c);
        }
        __syncthreads();

        // S = Q K^T (outer-product over d)
        float sc[4][4];
        #pragma unroll
        for (int i = 0; i < 4; i++)
            #pragma unroll
            for (int j = 0; j < 4; j++) sc[i][j] = 0.f;
        #pragma unroll 8
        for (int kk = 0; kk < 64; kk++) {
            float4 qa = *(const float4*)(QsT + kk*64 + ty*4);
            float4 kb = *(const float4*)(KsT + kk*64 + tx*4);
            float aa[4] = {qa.x, qa.y, qa.z, qa.w};
            float bb[4] = {kb.x, kb.y, kb.z, kb.w};
            #pragma unroll
            for (int i = 0; i < 4; i++)
                #pragma unroll
                for (int j = 0; j < 4; j++)
                    sc[i][j] = fmaf(aa[i], bb[j], sc[i][j]);
        }

        // mask: sc -= (1 - m) * 1e6  ==  sc += (m - 1) * 1e6
        #pragma unroll
        for (int i = 0; i < 4; i++) {
            const float4 mv = *(const float4*)(mask + ((size_t)b*NS + (q0 + ty*4 + i))*NS + j0 + tx*4);
            sc[i][0] = fmaf(mv.x - 1.0f, 1e6f, sc[i][0]);
            sc[i][1] = fmaf(mv.y - 1.0f, 1e6f, sc[i][1]);
            sc[i][2] = fmaf(mv.z - 1.0f, 1e6f, sc[i][2]);
            sc[i][3] = fmaf(mv.w - 1.0f, 1e6f, sc[i][3]);
        }

        // online softmax (row stats reduced over the 16 tx lanes)
        #pragma unroll
        for (int i = 0; i < 4; i++) {
            float cm = fmaxf(fmaxf(sc[i][0], sc[i][1]), fmaxf(sc[i][2], sc[i][3]));
            cm = fmaxf(cm, __shfl_xor_sync(0xffffffffu, cm, 1));
            cm = fmaxf(cm, __shfl_xor_sync(0xffffffffu, cm, 2));
            cm = fmaxf(cm, __shfl_xor_sync(0xffffffffu, cm, 4));
            cm = fmaxf(cm, __shfl_xor_sync(0xffffffffu, cm, 8));
            const float mn = fmaxf(mrow[i], cm);
            const float al = __expf(mrow[i] - mn);
            float rs = 0.f;
            #pragma unroll
            for (int j = 0; j < 4; j++) { sc[i][j] = __expf(sc[i][j] - mn); rs += sc[i][j]; }
            rs += __shfl_xor_sync(0xffffffffu, rs, 1);
            rs += __shfl_xor_sync(0xffffffffu, rs, 2);
            rs += __shfl_xor_sync(0xffffffffu, rs, 4);
            rs += __shfl_xor_sync(0xffffffffu, rs, 8);
            lsum[i] = lsum[i]*al + rs;
            mrow[i] = mn;
            #pragma unroll
            for (int j = 0; j < 4; j++) o[i][j] *= al;
        }

        // stage P to smem (natural layout, float4 stores, conflict-free)
        #pragma unroll
        for (int i = 0; i < 4; i++) {
            float4 pv = make_float4(sc[i][0], sc[i][1], sc[i][2], sc[i][3]);
            *(float4*)(Ps + (ty*4 + i)*64 + tx*4) = pv;
        }
        __syncthreads();

        // O += P @ V
        #pragma unroll 2
        for (int c4 = 0; c4 < 64; c4 += 4) {
            float pr[4][4];
            #pragma unroll
            for (int i = 0; i < 4; i++) {
                float4 p = *(const float4*)(Ps + (ty*4 + i)*64 + c4);
                pr[i][0] = p.x; pr[i][1] = p.y; pr[i][2] = p.z; pr[i][3] = p.w;
            }
            #pragma unroll
            for (int u = 0; u < 4; u++) {
                float4 vb = *(const float4*)(Vs + (c4 + u)*64 + tx*4);
                float bb[4] = {vb.x, vb.y, vb.z, vb.w};
                #pragma unroll
                for (int i = 0; i < 4; i++)
                    #pragma unroll
                    for (int j = 0; j < 4; j++)
                        o[i][j] = fmaf(pr[i][u], bb[j], o[i][j]);
            }
        }
    }

    // epilogue: normalize and write [B, S, H*64]
    #pragma unroll
    for (int i = 0; i < 4; i++) {
        const float inv = 1.0f / lsum[i];
        const int s = q0 + ty*4 + i;
        float4 v = make_float4(o[i][0]*inv, o[i][1]*inv, o[i][2]*inv, o[i][3]*inv);
        *(float4*)(out + ((size_t)b*NS + s)*NE + h*ND + tx*4) = v;
    }
}

extern "C" void kernel_launch(void* const* d_in, const int* in_sizes, int n_in,
                              void* d_out, int out_size)
{
    const float* query = (const float*)d_in[0];
    const float* key   = (const float*)d_in[1];
    const float* value = (const float*)d_in[2];
    const float* mask  = (const float*)d_in[3];
    const float* Wq    = (const float*)d_in[4];
    const float* bq    = (const float*)d_in[5];
    const float* Wk    = (const float*)d_in[6];
    const float* bk    = (const float*)d_in[7];
    const float* Wv    = (const float*)d_in[8];
    const float* bv    = (const float*)d_in[9];
    float* out = (float*)d_out;

    float *qp, *kp, *vp;
    cudaGetSymbolAddress((void**)&qp, g_Q);
    cudaGetSymbolAddress((void**)&kp, g_K);
    cudaGetSymbolAddress((void**)&vp, g_V);

    dim3 pg(NE/128, (NB*NS)/128);   // (8, 32)
    proj128<<<pg, 256>>>(query, Wq, bq, qp, 0.125f);   // 64^-0.5
    proj128<<<pg, 256>>>(key,   Wk, bk, kp, 1.0f);
    proj128<<<pg, 256>>>(value, Wv, bv, vp, 1.0f);

    cudaFuncSetAttribute(attn_kernel, cudaFuncAttributeMaxDynamicSharedMemorySize, 65536);
    dim3 ag(NS/64, NH, NB);
    attn_kernel<<<ag, 256, 65536>>>(mask, out);
}

// round 4
// speedup vs baseline: 1.1810x; 1.1810x over previous
#include <cuda_runtime.h>
#include <cstdint>
#include <math.h>

#define NB 4
#define NH 16
#define NS 1024
#define ND 64
#define NE 1024

// Scratch for projected Q/K/V in [B, H, S, 64] layout.
__device__ float g_Q[NB*NH*NS*ND];
__device__ float g_K[NB*NH*NS*ND];
__device__ float g_V[NB*NH*NS*ND];

// ---------------------------------------------------------------------------
// helpers
// ---------------------------------------------------------------------------
__device__ __forceinline__ uint32_t smem_u32(const void* p) {
    uint32_t a;
    asm("{ .reg .u64 t; cvta.to.shared.u64 t, %1; cvt.u32.u64 %0, t; }" : "=r"(a) : "l"(p));
    return a;
}
__device__ __forceinline__ void cp16s(uint32_t dst, const void* src) {
    asm volatile("cp.async.cg.shared.global [%0], [%1], 16;" :: "r"(dst), "l"(src));
}
#define CP_COMMIT() asm volatile("cp.async.commit_group;" ::: "memory")
#define CP_WAIT1()  asm volatile("cp.async.wait_group 1;"  ::: "memory")

// round-to-nearest tf32 (zeroes low 13 mantissa bits with rounding)
__device__ __forceinline__ uint32_t tf32_rna(float x) {
    uint32_t r; asm("cvt.rna.tf32.f32 %0, %1;" : "=r"(r) : "f"(x)); return r;
}

// tf32 m16n8k8 mma.sync on raw b32 fragments
__device__ __forceinline__ void mma8u(float* d, const uint32_t* a, const uint32_t* b) {
    asm volatile(
        "mma.sync.aligned.m16n8k8.row.col.f32.tf32.tf32.f32 "
        "{%0,%1,%2,%3}, {%4,%5,%6,%7}, {%8,%9}, {%0,%1,%2,%3};"
        : "+f"(d[0]), "+f"(d[1]), "+f"(d[2]), "+f"(d[3])
        : "r"(a[0]), "r"(a[1]), "r"(a[2]), "r"(a[3]), "r"(b[0]), "r"(b[1]));
}

// ---------------------------------------------------------------------------
// 3xTF32 mma.sync projection: out[(b,h,s,d)] = (X @ W^T + bias) * scale
// CTA tile 128x128, BK=32, 8 warps (warp tile 32x64), 2-stage cp.async.
// Each fp32 operand split hi/lo; accumulate hi*hi + hi*lo + lo*hi (fp32 acc).
// blockIdx.z in {0,1,2} selects Q/K/V.
// ---------------------------------------------------------------------------
#define BM 128
#define BN 128
#define BK 32
#define LDA 36
#define ASZ (BM*LDA)        // 4608 floats per operand tile
#define STGF (2*ASZ)        // 9216 floats per stage
#define NIT (NE/BK)         // 32

__device__ __forceinline__ void stage_load(uint32_t sbase, const float* __restrict__ X,
                                           const float* __restrict__ W,
                                           int m0, int n0, int it, int tid)
{
    const float* xa = X + (size_t)m0 * NE + it * BK;
    const float* wb = W + (size_t)n0 * NE + it * BK;
    #pragma unroll
    for (int i = 0; i < 4; i++) {
        int q = tid + i * 256;            // 0..1023 quads (128 rows x 8)
        int r = q >> 3, c = q & 7;
        cp16s(sbase + (uint32_t)(r * LDA + c * 4) * 4, xa + (size_t)r * NE + c * 4);
    }
    #pragma unroll
    for (int i = 0; i < 4; i++) {
        int q = tid + i * 256;
        int r = q >> 3, c = q & 7;
        cp16s(sbase + (uint32_t)(ASZ + r * LDA + c * 4) * 4, wb + (size_t)r * NE + c * 4);
    }
}

__global__ __launch_bounds__(256, 1) void proj_tc(
    const float* __restrict__ Xq, const float* __restrict__ Xk, const float* __restrict__ Xv,
    const float* __restrict__ Wq, const float* __restrict__ Wk, const float* __restrict__ Wv,
    const float* __restrict__ Bq, const float* __restrict__ Bk, const float* __restrict__ Bv,
    float* __restrict__ Oq, float* __restrict__ Ok, float* __restrict__ Ov)
{
    extern __shared__ float sm[];
    const uint32_t sb = smem_u32(sm);

    const int tid = threadIdx.x;
    const int z = blockIdx.z;
    const float* X  = (z == 0) ? Xq : (z == 1) ? Xk : Xv;
    const float* W  = (z == 0) ? Wq : (z == 1) ? Wk : Wv;
    const float* Bi = (z == 0) ? Bq : (z == 1) ? Bk : Bv;
    float* out = (z == 0) ? Oq : (z == 1) ? Ok : Ov;
    const float scale = (z == 0) ? 0.125f : 1.0f;

    const int m0 = blockIdx.y * BM;
    const int n0 = blockIdx.x * BN;

    const int warp = tid >> 5, lane = tid & 31;
    const int g = lane >> 2, tig = lane & 3;
    const int wm = warp >> 1, wn = warp & 1;     // 4 x 2 warp grid

    float cfr[2][8][4];
    #pragma unroll
    for (int mt = 0; mt < 2; mt++)
        #pragma unroll
        for (int nt = 0; nt < 8; nt++)
            #pragma unroll
            for (int e = 0; e < 4; e++) cfr[mt][nt][e] = 0.f;

    stage_load(sb, X, W, m0, n0, 0, tid);
    CP_COMMIT();

    for (int it = 0; it < NIT; it++) {
        if (it + 1 < NIT)
            stage_load(sb + ((it + 1) & 1) * STGF * 4, X, W, m0, n0, it + 1, tid);
        CP_COMMIT();                         // empty group on last iter keeps count uniform
        CP_WAIT1();
        __syncthreads();

        const float* As = sm + (it & 1) * STGF;
        const float* Bs = As + ASZ;

        #pragma unroll
        for (int ks = 0; ks < 4; ks++) {
            const int k0 = ks * 8;
            // load fp32 fragments from smem
            float a[2][4];
            #pragma unroll
            for (int mt = 0; mt < 2; mt++) {
                const int r0 = wm * 32 + mt * 16 + g;
                a[mt][0] = As[(r0    ) * LDA + k0 + tig];
                a[mt][1] = As[(r0 + 8) * LDA + k0 + tig];
                a[mt][2] = As[(r0    ) * LDA + k0 + tig + 4];
                a[mt][3] = As[(r0 + 8) * LDA + k0 + tig + 4];
            }
            float b[8][2];
            #pragma unroll
            for (int nt = 0; nt < 8; nt++) {
                const int rn = wn * 64 + nt * 8 + g;
                b[nt][0] = Bs[rn * LDA + k0 + tig];
                b[nt][1] = Bs[rn * LDA + k0 + tig + 4];
            }
            // hi/lo splits
            uint32_t ah[2][4], al[2][4];
            #pragma unroll
            for (int mt = 0; mt < 2; mt++)
                #pragma unroll
                for (int e = 0; e < 4; e++) {
                    ah[mt][e] = tf32_rna(a[mt][e]);
                    al[mt][e] = __float_as_uint(a[mt][e] - __uint_as_float(ah[mt][e]));
                }
            uint32_t bh[8][2], bl[8][2];
            #pragma unroll
            for (int nt = 0; nt < 8; nt++)
                #pragma unroll
                for (int e = 0; e < 2; e++) {
                    bh[nt][e] = tf32_rna(b[nt][e]);
                    bl[nt][e] = __float_as_uint(b[nt][e] - __uint_as_float(bh[nt][e]));
                }
            // 3xTF32: hi*lo + lo*hi first (small terms), then hi*hi
            #pragma unroll
            for (int mt = 0; mt < 2; mt++)
                #pragma unroll
                for (int nt = 0; nt < 8; nt++) {
                    mma8u(cfr[mt][nt], ah[mt], bl[nt]);
                    mma8u(cfr[mt][nt], al[mt], bh[nt]);
                    mma8u(cfr[mt][nt], ah[mt], bh[nt]);
                }
        }
        __syncthreads();
    }

    // Epilogue: stage C in smem (128 x 132), then coalesced permuted store.
    float* Cs = sm;
    #pragma unroll
    for (int mt = 0; mt < 2; mt++) {
        const int rm = wm * 32 + mt * 16 + g;
        #pragma unroll
        for (int nt = 0; nt < 8; nt++) {
            const int cn = wn * 64 + nt * 8 + 2 * tig;
            Cs[(rm    ) * 132 + cn    ] = cfr[mt][nt][0];
            Cs[(rm    ) * 132 + cn + 1] = cfr[mt][nt][1];
            Cs[(rm + 8) * 132 + cn    ] = cfr[mt][nt][2];
            Cs[(rm + 8) * 132 + cn + 1] = cfr[mt][nt][3];
        }
    }
    __syncthreads();

    const int qcol = (tid & 15) * 4;
    #pragma unroll
    for (int hh = 0; hh < 2; hh++) {
        const int h = (n0 >> 6) + hh;
        const float4 bv = *(const float4*)(Bi + n0 + hh * 64 + qcol);
        #pragma unroll
        for (int p = 0; p < 8; p++) {
            const int idx = tid + p * 256;       // 0..2047
            const int m = idx >> 4;
            const int gm = m0 + m, b = gm >> 10, s = gm & (NS - 1);
            const float* src = Cs + m * 132 + hh * 64 + qcol;
            float4 v;
            v.x = (src[0] + bv.x) * scale;
            v.y = (src[1] + bv.y) * scale;
            v.z = (src[2] + bv.z) * scale;
            v.w = (src[3] + bv.w) * scale;
            *(float4*)(out + ((size_t)(b * NH + h) * NS + s) * ND + qcol) = v;
        }
    }
}

// ---------------------------------------------------------------------------
// Fused flash-style attention (unchanged from R1, known-good, 565 us).
// ---------------------------------------------------------------------------
__global__ __launch_bounds__(256) void attn_kernel(const float* __restrict__ mask,
                                                   float* __restrict__ out)
{
    extern __shared__ float smf[];
    float* QsT = smf;
    float* KsT = smf + 4096;
    float* Vs  = smf + 8192;
    float* Ps  = smf + 12288;

    const int b  = blockIdx.z, h = blockIdx.y;
    const int q0 = blockIdx.x * 64;
    const int tid = threadIdx.x;
    const int ty = tid >> 4, tx = tid & 15;
    const int lrow = tid >> 2;
    const int lk4  = (tid & 3) << 2;

    const size_t base = (size_t)((b*NH + h)*NS) * ND;
    const float* Qg = g_Q + base;
    const float* Kg = g_K + base;
    const float* Vg = g_V + base;

    #pragma unroll
    for (int rep = 0; rep < 4; rep++) {
        const int c = lk4 + rep*16;
        float4 a = *(const float4*)(Qg + (q0 + lrow)*ND + c);
        QsT[(c+0)*64 + lrow] = a.x; QsT[(c+1)*64 + lrow] = a.y;
        QsT[(c+2)*64 + lrow] = a.z; QsT[(c+3)*64 + lrow] = a.w;
    }

    float o[4][4];
    #pragma unroll
    for (int i = 0; i < 4; i++)
        #pragma unroll
        for (int j = 0; j < 4; j++) o[i][j] = 0.f;
    float mrow[4] = {-3.4e38f, -3.4e38f, -3.4e38f, -3.4e38f};
    float lsum[4] = {0.f, 0.f, 0.f, 0.f};

    for (int jt = 0; jt < NS/64; jt++) {
        const int j0 = jt * 64;
        __syncthreads();
        #pragma unroll
        for (int rep = 0; rep < 4; rep++) {
            const int c = lk4 + rep*16;
            float4 kv = *(const float4*)(Kg + (j0 + lrow)*ND + c);
            KsT[(c+0)*64 + lrow] = kv.x; KsT[(c+1)*64 + lrow] = kv.y;
            KsT[(c+2)*64 + lrow] = kv.z; KsT[(c+3)*64 + lrow] = kv.w;
            *(float4*)(Vs + lrow*64 + c) = *(const float4*)(Vg + (j0 + lrow)*ND + c);
        }
        __syncthreads();

        float sc[4][4];
        #pragma unroll
        for (int i = 0; i < 4; i++)
            #pragma unroll
            for (int j = 0; j < 4; j++) sc[i][j] = 0.f;
        #pragma unroll 8
        for (int kk = 0; kk < 64; kk++) {
            float4 qa = *(const float4*)(QsT + kk*64 + ty*4);
            float4 kb = *(const float4*)(KsT + kk*64 + tx*4);
            float aa[4] = {qa.x, qa.y, qa.z, qa.w};
            float bb[4] = {kb.x, kb.y, kb.z, kb.w};
            #pragma unroll
            for (int i = 0; i < 4; i++)
                #pragma unroll
                for (int j = 0; j < 4; j++)
                    sc[i][j] = fmaf(aa[i], bb[j], sc[i][j]);
        }

        #pragma unroll
        for (int i = 0; i < 4; i++) {
            const float4 mv = *(const float4*)(mask + ((size_t)b*NS + (q0 + ty*4 + i))*NS + j0 + tx*4);
            sc[i][0] = fmaf(mv.x - 1.0f, 1e6f, sc[i][0]);
            sc[i][1] = fmaf(mv.y - 1.0f, 1e6f, sc[i][1]);
            sc[i][2] = fmaf(mv.z - 1.0f, 1e6f, sc[i][2]);
            sc[i][3] = fmaf(mv.w - 1.0f, 1e6f, sc[i][3]);
        }

        #pragma unroll
        for (int i = 0; i < 4; i++) {
            float cm = fmaxf(fmaxf(sc[i][0], sc[i][1]), fmaxf(sc[i][2], sc[i][3]));
            cm = fmaxf(cm, __shfl_xor_sync(0xffffffffu, cm, 1));
            cm = fmaxf(cm, __shfl_xor_sync(0xffffffffu, cm, 2));
            cm = fmaxf(cm, __shfl_xor_sync(0xffffffffu, cm, 4));
            cm = fmaxf(cm, __shfl_xor_sync(0xffffffffu, cm, 8));
            const float mn = fmaxf(mrow[i], cm);
            const float al = __expf(mrow[i] - mn);
            float rs = 0.f;
            #pragma unroll
            for (int j = 0; j < 4; j++) { sc[i][j] = __expf(sc[i][j] - mn); rs += sc[i][j]; }
            rs += __shfl_xor_sync(0xffffffffu, rs, 1);
            rs += __shfl_xor_sync(0xffffffffu, rs, 2);
            rs += __shfl_xor_sync(0xffffffffu, rs, 4);
            rs += __shfl_xor_sync(0xffffffffu, rs, 8);
            lsum[i] = lsum[i]*al + rs;
            mrow[i] = mn;
            #pragma unroll
            for (int j = 0; j < 4; j++) o[i][j] *= al;
        }

        #pragma unroll
        for (int i = 0; i < 4; i++) {
            float4 pv = make_float4(sc[i][0], sc[i][1], sc[i][2], sc[i][3]);
            *(float4*)(Ps + (ty*4 + i)*64 + tx*4) = pv;
        }
        __syncthreads();

        #pragma unroll 2
        for (int c4 = 0; c4 < 64; c4 += 4) {
            float pr[4][4];
            #pragma unroll
            for (int i = 0; i < 4; i++) {
                float4 p = *(const float4*)(Ps + (ty*4 + i)*64 + c4);
                pr[i][0] = p.x; pr[i][1] = p.y; pr[i][2] = p.z; pr[i][3] = p.w;
            }
            #pragma unroll
            for (int u = 0; u < 4; u++) {
                float4 vb = *(const float4*)(Vs + (c4 + u)*64 + tx*4);
                float bb[4] = {vb.x, vb.y, vb.z, vb.w};
                #pragma unroll
                for (int i = 0; i < 4; i++)
                    #pragma unroll
                    for (int j = 0; j < 4; j++)
                        o[i][j] = fmaf(pr[i][u], bb[j], o[i][j]);
            }
        }
    }

    #pragma unroll
    for (int i = 0; i < 4; i++) {
        const float inv = 1.0f / lsum[i];
        const int s = q0 + ty*4 + i;
        float4 v = make_float4(o[i][0]*inv, o[i][1]*inv, o[i][2]*inv, o[i][3]*inv);
        *(float4*)(out + ((size_t)b*NS + s)*NE + h*ND + tx*4) = v;
    }
}

extern "C" void kernel_launch(void* const* d_in, const int* in_sizes, int n_in,
                              void* d_out, int out_size)
{
    const float* query = (const float*)d_in[0];
    const float* key   = (const float*)d_in[1];
    const float* value = (const float*)d_in[2];
    const float* mask  = (const float*)d_in[3];
    const float* Wq    = (const float*)d_in[4];
    const float* bq    = (const float*)d_in[5];
    const float* Wk    = (const float*)d_in[6];
    const float* bk    = (const float*)d_in[7];
    const float* Wv    = (const float*)d_in[8];
    const float* bv    = (const float*)d_in[9];
    float* out = (float*)d_out;

    float *qp, *kp, *vp;
    cudaGetSymbolAddress((void**)&qp, g_Q);
    cudaGetSymbolAddress((void**)&kp, g_K);
    cudaGetSymbolAddress((void**)&vp, g_V);

    const int proj_smem = 2 * STGF * 4;   // 73728 B
    cudaFuncSetAttribute(proj_tc, cudaFuncAttributeMaxDynamicSharedMemorySize, proj_smem);
    dim3 pg(NE / BN, (NB * NS) / BM, 3);   // (8, 32, 3)
    proj_tc<<<pg, 256, proj_smem>>>(query, key, value, Wq, Wk, Wv, bq, bk, bv, qp, kp, vp);

    cudaFuncSetAttribute(attn_kernel, cudaFuncAttributeMaxDynamicSharedMemorySize, 65536);
    dim3 ag(NS/64, NH, NB);
    attn_kernel<<<ag, 256, 65536>>>(mask, out);
}

// round 6
// speedup vs baseline: 1.3394x; 1.1341x over previous
#include <cuda_runtime.h>
#include <cstdint>
#include <math.h>

#define NB 4
#define NH 16
#define NS 1024
#define ND 64
#define NE 1024

// Scratch for projected Q/K/V in [B, H, S, 64] layout.
__device__ float g_Q[NB*NH*NS*ND];
__device__ float g_K[NB*NH*NS*ND];
__device__ float g_V[NB*NH*NS*ND];

// ---------------------------------------------------------------------------
// helpers
// ---------------------------------------------------------------------------
__device__ __forceinline__ uint32_t smem_u32(const void* p) {
    uint32_t a;
    asm("{ .reg .u64 t; cvta.to.shared.u64 t, %1; cvt.u32.u64 %0, t; }" : "=r"(a) : "l"(p));
    return a;
}
__device__ __forceinline__ void cp16s(uint32_t dst, const void* src) {
    asm volatile("cp.async.cg.shared.global [%0], [%1], 16;" :: "r"(dst), "l"(src));
}
#define CP_COMMIT() asm volatile("cp.async.commit_group;" ::: "memory")
#define CP_WAIT1()  asm volatile("cp.async.wait_group 1;"  ::: "memory")

// round-to-nearest tf32 (zeroes low 13 mantissa bits with rounding)
__device__ __forceinline__ uint32_t tf32_rna(float x) {
    uint32_t r; asm("cvt.rna.tf32.f32 %0, %1;" : "=r"(r) : "f"(x)); return r;
}
__device__ __forceinline__ void split_hl(float x, uint32_t& h, uint32_t& l) {
    h = tf32_rna(x);
    l = __float_as_uint(x - __uint_as_float(h));
}

// tf32 m16n8k8 mma.sync on raw b32 fragments
__device__ __forceinline__ void mma8u(float* d, const uint32_t* a, const uint32_t* b) {
    asm volatile(
        "mma.sync.aligned.m16n8k8.row.col.f32.tf32.tf32.f32 "
        "{%0,%1,%2,%3}, {%4,%5,%6,%7}, {%8,%9}, {%0,%1,%2,%3};"
        : "+f"(d[0]), "+f"(d[1]), "+f"(d[2]), "+f"(d[3])
        : "r"(a[0]), "r"(a[1]), "r"(a[2]), "r"(a[3]), "r"(b[0]), "r"(b[1]));
}

// ---------------------------------------------------------------------------
// 3xTF32 mma.sync projection (validated in R4, rel_err 2.3e-5).
// ---------------------------------------------------------------------------
#define BM 128
#define BN 128
#define BK 32
#define LDA 36
#define ASZ (BM*LDA)
#define STGF (2*ASZ)
#define NIT (NE/BK)

__device__ __forceinline__ void stage_load(uint32_t sbase, const float* __restrict__ X,
                                           const float* __restrict__ W,
                                           int m0, int n0, int it, int tid)
{
    const float* xa = X + (size_t)m0 * NE + it * BK;
    const float* wb = W + (size_t)n0 * NE + it * BK;
    #pragma unroll
    for (int i = 0; i < 4; i++) {
        int q = tid + i * 256;
        int r = q >> 3, c = q & 7;
        cp16s(sbase + (uint32_t)(r * LDA + c * 4) * 4, xa + (size_t)r * NE + c * 4);
    }
    #pragma unroll
    for (int i = 0; i < 4; i++) {
        int q = tid + i * 256;
        int r = q >> 3, c = q & 7;
        cp16s(sbase + (uint32_t)(ASZ + r * LDA + c * 4) * 4, wb + (size_t)r * NE + c * 4);
    }
}

__global__ __launch_bounds__(256, 1) void proj_tc(
    const float* __restrict__ Xq, const float* __restrict__ Xk, const float* __restrict__ Xv,
    const float* __restrict__ Wq, const float* __restrict__ Wk, const float* __restrict__ Wv,
    const float* __restrict__ Bq, const float* __restrict__ Bk, const float* __restrict__ Bv,
    float* __restrict__ Oq, float* __restrict__ Ok, float* __restrict__ Ov)
{
    extern __shared__ float sm[];
    const uint32_t sb = smem_u32(sm);

    const int tid = threadIdx.x;
    const int z = blockIdx.z;
    const float* X  = (z == 0) ? Xq : (z == 1) ? Xk : Xv;
    const float* W  = (z == 0) ? Wq : (z == 1) ? Wk : Wv;
    const float* Bi = (z == 0) ? Bq : (z == 1) ? Bk : Bv;
    float* out = (z == 0) ? Oq : (z == 1) ? Ok : Ov;
    const float scale = (z == 0) ? 0.125f : 1.0f;

    const int m0 = blockIdx.y * BM;
    const int n0 = blockIdx.x * BN;

    const int warp = tid >> 5, lane = tid & 31;
    const int g = lane >> 2, tig = lane & 3;
    const int wm = warp >> 1, wn = warp & 1;

    float cfr[2][8][4];
    #pragma unroll
    for (int mt = 0; mt < 2; mt++)
        #pragma unroll
        for (int nt = 0; nt < 8; nt++)
            #pragma unroll
            for (int e = 0; e < 4; e++) cfr[mt][nt][e] = 0.f;

    stage_load(sb, X, W, m0, n0, 0, tid);
    CP_COMMIT();

    for (int it = 0; it < NIT; it++) {
        if (it + 1 < NIT)
            stage_load(sb + ((it + 1) & 1) * STGF * 4, X, W, m0, n0, it + 1, tid);
        CP_COMMIT();
        CP_WAIT1();
        __syncthreads();

        const float* As = sm + (it & 1) * STGF;
        const float* Bs = As + ASZ;

        #pragma unroll
        for (int ks = 0; ks < 4; ks++) {
            const int k0 = ks * 8;
            float a[2][4];
            #pragma unroll
            for (int mt = 0; mt < 2; mt++) {
                const int r0 = wm * 32 + mt * 16 + g;
                a[mt][0] = As[(r0    ) * LDA + k0 + tig];
                a[mt][1] = As[(r0 + 8) * LDA + k0 + tig];
                a[mt][2] = As[(r0    ) * LDA + k0 + tig + 4];
                a[mt][3] = As[(r0 + 8) * LDA + k0 + tig + 4];
            }
            float b[8][2];
            #pragma unroll
            for (int nt = 0; nt < 8; nt++) {
                const int rn = wn * 64 + nt * 8 + g;
                b[nt][0] = Bs[rn * LDA + k0 + tig];
                b[nt][1] = Bs[rn * LDA + k0 + tig + 4];
            }
            uint32_t ah[2][4], al[2][4];
            #pragma unroll
            for (int mt = 0; mt < 2; mt++)
                #pragma unroll
                for (int e = 0; e < 4; e++) split_hl(a[mt][e], ah[mt][e], al[mt][e]);
            uint32_t bh[8][2], bl[8][2];
            #pragma unroll
            for (int nt = 0; nt < 8; nt++)
                #pragma unroll
                for (int e = 0; e < 2; e++) split_hl(b[nt][e], bh[nt][e], bl[nt][e]);
            #pragma unroll
            for (int mt = 0; mt < 2; mt++)
                #pragma unroll
                for (int nt = 0; nt < 8; nt++) {
                    mma8u(cfr[mt][nt], ah[mt], bl[nt]);
                    mma8u(cfr[mt][nt], al[mt], bh[nt]);
                    mma8u(cfr[mt][nt], ah[mt], bh[nt]);
                }
        }
        __syncthreads();
    }

    float* Cs = sm;
    #pragma unroll
    for (int mt = 0; mt < 2; mt++) {
        const int rm = wm * 32 + mt * 16 + g;
        #pragma unroll
        for (int nt = 0; nt < 8; nt++) {
            const int cn = wn * 64 + nt * 8 + 2 * tig;
            Cs[(rm    ) * 132 + cn    ] = cfr[mt][nt][0];
            Cs[(rm    ) * 132 + cn + 1] = cfr[mt][nt][1];
            Cs[(rm + 8) * 132 + cn    ] = cfr[mt][nt][2];
            Cs[(rm + 8) * 132 + cn + 1] = cfr[mt][nt][3];
        }
    }
    __syncthreads();

    const int qcol = (tid & 15) * 4;
    #pragma unroll
    for (int hh = 0; hh < 2; hh++) {
        const int h = (n0 >> 6) + hh;
        const float4 bv = *(const float4*)(Bi + n0 + hh * 64 + qcol);
        #pragma unroll
        for (int p = 0; p < 8; p++) {
            const int idx = tid + p * 256;
            const int m = idx >> 4;
            const int gm = m0 + m, b = gm >> 10, s = gm & (NS - 1);
            const float* src = Cs + m * 132 + hh * 64 + qcol;
            float4 v;
            v.x = (src[0] + bv.x) * scale;
            v.y = (src[1] + bv.y) * scale;
            v.z = (src[2] + bv.z) * scale;
            v.w = (src[3] + bv.w) * scale;
            *(float4*)(out + ((size_t)(b * NH + h) * NS + s) * ND + qcol) = v;
        }
    }
}

// ---------------------------------------------------------------------------
// Tensor-core flash attention. CTA = (b, h, 64-query tile), 4 warps (128 thr),
// warp owns 16 query rows. Scores 3xTF32, PV 2xTF32 (Ph*Vh + Pl*Vh).
// Smem strides conflict-free: Qs/Ps/Ks=68 (g-indexed rows), Vs=72 (tig-indexed).
// ---------------------------------------------------------------------------
#define LQ 68
#define LV 72

__global__ __launch_bounds__(128) void attn_tc(const float* __restrict__ mask,
                                               float* __restrict__ out)
{
    extern __shared__ float s[];
    float* Qs = s;                    // [64][LQ]
    float* Ps = s + 64*LQ;            // [64][LQ]
    float* Ks = s + 2*64*LQ;          // [64][LQ]
    float* Vs = s + 3*64*LQ;          // [64][LV]

    const int b = blockIdx.z, h = blockIdx.y;
    const int q0 = blockIdx.x * 64;
    const int tid = threadIdx.x, warp = tid >> 5, lane = tid & 31;
    const int g = lane >> 2, tig = lane & 3;
    const int r0 = warp * 16 + g;     // this thread's first query row (of 2)

    const size_t base = (size_t)((b*NH + h)*NS) * ND;
    const float* Qg = g_Q + base;
    const float* Kg = g_K + base;
    const float* Vg = g_V + base;

    // Q tile -> Qs (persists whole kernel)
    #pragma unroll
    for (int i = 0; i < 8; i++) {
        int idx = tid + i * 128;
        int r = idx >> 4, q = idx & 15;
        *(float4*)(Qs + r*LQ + q*4) = *(const float4*)(Qg + (q0 + r)*ND + q*4);
    }

    float o[8][4];
    #pragma unroll
    for (int nt = 0; nt < 8; nt++)
        #pragma unroll
        for (int e = 0; e < 4; e++) o[nt][e] = 0.f;
    float mrow[2] = {-3.4e38f, -3.4e38f};
    float lsum[2] = {0.f, 0.f};

    for (int jt = 0; jt < NS/64; jt++) {
        const int j0 = jt * 64;
        __syncthreads();                       // prev iter Ks/Vs reads done
        #pragma unroll
        for (int i = 0; i < 8; i++) {
            int idx = tid + i * 128;
            int r = idx >> 4, q = idx & 15;
            *(float4*)(Ks + r*LQ + q*4) = *(const float4*)(Kg + (j0 + r)*ND + q*4);
            *(float4*)(Vs + r*LV + q*4) = *(const float4*)(Vg + (j0 + r)*ND + q*4);
        }
        __syncthreads();

        // ---- scores: S[16 x 64] per warp, 3xTF32 ----
        float c[8][4];
        #pragma unroll
        for (int nt = 0; nt < 8; nt++)
            #pragma unroll
            for (int e = 0; e < 4; e++) c[nt][e] = 0.f;

        #pragma unroll
        for (int kc = 0; kc < 8; kc++) {
            const int k8 = kc * 8;
            uint32_t ah[4], al[4];
            split_hl(Qs[(r0    )*LQ + k8 + tig    ], ah[0], al[0]);
            split_hl(Qs[(r0 + 8)*LQ + k8 + tig    ], ah[1], al[1]);
            split_hl(Qs[(r0    )*LQ + k8 + tig + 4], ah[2], al[2]);
            split_hl(Qs[(r0 + 8)*LQ + k8 + tig + 4], ah[3], al[3]);
            #pragma unroll
            for (int nt = 0; nt < 8; nt++) {
                const float* kr = Ks + (nt*8 + g)*LQ + k8;
                uint32_t bh[2], bl[2];
                split_hl(kr[tig    ], bh[0], bl[0]);
                split_hl(kr[tig + 4], bh[1], bl[1]);
                mma8u(c[nt], ah, bl);
                mma8u(c[nt], al, bh);
                mma8u(c[nt], ah, bh);
            }
        }

        // ---- mask ----
        const float* mrow0 = mask + ((size_t)b*NS + (q0 + r0))*NS + j0 + 2*tig;
        #pragma unroll
        for (int nt = 0; nt < 8; nt++) {
            float2 m0 = *(const float2*)(mrow0 + nt*8);
            float2 m1 = *(const float2*)(mrow0 + (size_t)8*NS + nt*8);
            c[nt][0] = fmaf(m0.x - 1.f, 1e6f, c[nt][0]);
            c[nt][1] = fmaf(m0.y - 1.f, 1e6f, c[nt][1]);
            c[nt][2] = fmaf(m1.x - 1.f, 1e6f, c[nt][2]);
            c[nt][3] = fmaf(m1.y - 1.f, 1e6f, c[nt][3]);
        }

        // ---- online softmax (rows r0 and r0+8; reduce over 4 tig lanes) ----
        #pragma unroll
        for (int sl = 0; sl < 2; sl++) {
            float cm = -3.4e38f;
            #pragma unroll
            for (int nt = 0; nt < 8; nt++)
                cm = fmaxf(cm, fmaxf(c[nt][2*sl], c[nt][2*sl + 1]));
            cm = fmaxf(cm, __shfl_xor_sync(0xffffffffu, cm, 1));
            cm = fmaxf(cm, __shfl_xor_sync(0xffffffffu, cm, 2));
            const float mn = fmaxf(mrow[sl], cm);
            const float alc = __expf(mrow[sl] - mn);
            mrow[sl] = mn;
            float rs = 0.f;
            #pragma unroll
            for (int nt = 0; nt < 8; nt++) {
                c[nt][2*sl]     = __expf(c[nt][2*sl]     - mn);
                c[nt][2*sl + 1] = __expf(c[nt][2*sl + 1] - mn);
                rs += c[nt][2*sl] + c[nt][2*sl + 1];
            }
            rs += __shfl_xor_sync(0xffffffffu, rs, 1);
            rs += __shfl_xor_sync(0xffffffffu, rs, 2);
            lsum[sl] = lsum[sl] * alc + rs;
            #pragma unroll
            for (int nt = 0; nt < 8; nt++) {
                o[nt][2*sl]     *= alc;
                o[nt][2*sl + 1] *= alc;
            }
        }

        // ---- stage P (warp-private rows, only syncwarp needed) ----
        #pragma unroll
        for (int nt = 0; nt < 8; nt++) {
            *(float2*)(Ps + (r0    )*LQ + nt*8 + 2*tig) = make_float2(c[nt][0], c[nt][1]);
            *(float2*)(Ps + (r0 + 8)*LQ + nt*8 + 2*tig) = make_float2(c[nt][2], c[nt][3]);
        }
        __syncwarp();

        // ---- O += P @ V  (2xTF32: Ph*Vh + Pl*Vh) ----
        #pragma unroll
        for (int kc = 0; kc < 8; kc++) {
            const int k8 = kc * 8;
            uint32_t ah[4], al[4];
            split_hl(Ps[(r0    )*LQ + k8 + tig    ], ah[0], al[0]);
            split_hl(Ps[(r0 + 8)*LQ + k8 + tig    ], ah[1], al[1]);
            split_hl(Ps[(r0    )*LQ + k8 + tig + 4], ah[2], al[2]);
            split_hl(Ps[(r0 + 8)*LQ + k8 + tig + 4], ah[3], al[3]);
            #pragma unroll
            for (int nt = 0; nt < 8; nt++) {
                uint32_t bh[2];
                bh[0] = tf32_rna(Vs[(k8 + tig    )*LV + nt*8 + g]);
                bh[1] = tf32_rna(Vs[(k8 + tig + 4)*LV + nt*8 + g]);
                mma8u(o[nt], ah, bh);
                mma8u(o[nt], al, bh);
            }
        }
    }

    // ---- epilogue: normalize, write [B, S, H*64] ----
    const float inv0 = 1.0f / lsum[0];
    const float inv1 = 1.0f / lsum[1];
    float* orow0 = out + ((size_t)b*NS + (q0 + r0))*NE + h*ND + 2*tig;
    #pragma unroll
    for (int nt = 0; nt < 8; nt++) {
        *(float2*)(orow0 + nt*8) = make_float2(o[nt][0]*inv0, o[nt][1]*inv0);
        *(float2*)(orow0 + (size_t)8*NE + nt*8) = make_float2(o[nt][2]*inv1, o[nt][3]*inv1);
    }
}

extern "C" void kernel_launch(void* const* d_in, const int* in_sizes, int n_in,
                              void* d_out, int out_size)
{
    const float* query = (const float*)d_in[0];
    const float* key   = (const float*)d_in[1];
    const float* value = (const float*)d_in[2];
    const float* mask  = (const float*)d_in[3];
    const float* Wq    = (const float*)d_in[4];
    const float* bq    = (const float*)d_in[5];
    const float* Wk    = (const float*)d_in[6];
    const float* bk    = (const float*)d_in[7];
    const float* Wv    = (const float*)d_in[8];
    const float* bv    = (const float*)d_in[9];
    float* out = (float*)d_out;

    float *qp, *kp, *vp;
    cudaGetSymbolAddress((void**)&qp, g_Q);
    cudaGetSymbolAddress((void**)&kp, g_K);
    cudaGetSymbolAddress((void**)&vp, g_V);

    const int proj_smem = 2 * STGF * 4;   // 73728 B
    cudaFuncSetAttribute(proj_tc, cudaFuncAttributeMaxDynamicSharedMemorySize, proj_smem);
    dim3 pg(NE / BN, (NB * NS) / BM, 3);   // (8, 32, 3)
    proj_tc<<<pg, 256, proj_smem>>>(query, key, value, Wq, Wk, Wv, bq, bk, bv, qp, kp, vp);

    const int attn_smem = (3 * 64 * LQ + 64 * LV) * 4;   // 70656 B
    cudaFuncSetAttribute(attn_tc, cudaFuncAttributeMaxDynamicSharedMemorySize, attn_smem);
    dim3 ag(NS/64, NH, NB);
    attn_tc<<<ag, 128, attn_smem>>>(mask, out);
}

// round 7
// speedup vs baseline: 2.0242x; 1.5113x over previous
#include <cuda_runtime.h>
#include <cstdint>
#include <math.h>

#define NB 4
#define NH 16
#define NS 1024
#define ND 64
#define NE 1024

// ---------------------------------------------------------------------------
// Global scratch: bf16 hi/lo packed planes (u32 = 2 bf16, consecutive k).
// ---------------------------------------------------------------------------
__device__ uint32_t g_XH[3 * 4096 * 512];   // inputs  [z][m][kp]
__device__ uint32_t g_XL[3 * 4096 * 512];
__device__ uint32_t g_WH[3 * 1024 * 512];   // weights [z][n][kp]
__device__ uint32_t g_WL[3 * 1024 * 512];
__device__ uint32_t g_QH[NB*NH*NS*32];      // Q/K: [(b,h)][s][dp]
__device__ uint32_t g_QL[NB*NH*NS*32];
__device__ uint32_t g_KH[NB*NH*NS*32];
__device__ uint32_t g_KL[NB*NH*NS*32];
__device__ uint32_t g_VH[NB*NH*64*512];     // V: [(b,h)][d][sp]  (key-pair packed)
__device__ uint32_t g_VL[NB*NH*64*512];

// ---------------------------------------------------------------------------
// helpers
// ---------------------------------------------------------------------------
__device__ __forceinline__ uint32_t smem_u32(const void* p) {
    uint32_t a;
    asm("{ .reg .u64 t; cvta.to.shared.u64 t, %1; cvt.u32.u64 %0, t; }" : "=r"(a) : "l"(p));
    return a;
}
__device__ __forceinline__ void cp16s(uint32_t dst, const void* src) {
    asm volatile("cp.async.cg.shared.global [%0], [%1], 16;" :: "r"(dst), "l"(src));
}
#define CP_COMMIT() asm volatile("cp.async.commit_group;" ::: "memory")
#define CP_WAIT1()  asm volatile("cp.async.wait_group 1;"  ::: "memory")

// pack two fp32 into bf16x2 (lo_elem -> bits[15:0], hi_elem -> bits[31:16])
__device__ __forceinline__ uint32_t packbf(float e0, float e1) {
    uint32_t r; asm("cvt.rn.bf16x2.f32 %0, %1, %2;" : "=r"(r) : "f"(e1), "f"(e0)); return r;
}
// split pair into hi plane + lo (residual) plane
__device__ __forceinline__ void split2(float x0, float x1, uint32_t& h, uint32_t& l) {
    h = packbf(x0, x1);
    float h0 = __uint_as_float(h << 16);
    float h1 = __uint_as_float(h & 0xffff0000u);
    l = packbf(x0 - h0, x1 - h1);
}

// bf16 m16n8k16 mma.sync
__device__ __forceinline__ void mma16(float* d, const uint32_t* a, const uint32_t* b) {
    asm volatile(
        "mma.sync.aligned.m16n8k16.row.col.f32.bf16.bf16.f32 "
        "{%0,%1,%2,%3}, {%4,%5,%6,%7}, {%8,%9}, {%0,%1,%2,%3};"
        : "+f"(d[0]), "+f"(d[1]), "+f"(d[2]), "+f"(d[3])
        : "r"(a[0]), "r"(a[1]), "r"(a[2]), "r"(a[3]), "r"(b[0]), "r"(b[1]));
}

// ---------------------------------------------------------------------------
// Pre-pass: split 6 fp32 tensors into bf16 hi/lo packed planes.
// z 0..2 : inputs (4096x1024) ; z 3..5 : weights (1024x1024)
// ---------------------------------------------------------------------------
__global__ void split_in(const float* __restrict__ q, const float* __restrict__ k,
                         const float* __restrict__ v, const float* __restrict__ wq,
                         const float* __restrict__ wk, const float* __restrict__ wv)
{
    const int z = blockIdx.y;
    const float* src; uint32_t* H; uint32_t* L; int n;
    if (z < 3) {
        src = (z == 0) ? q : (z == 1) ? k : v;
        H = g_XH + (size_t)z * 4096 * 512; L = g_XL + (size_t)z * 4096 * 512;
        n = 4096 * 512;
    } else {
        src = (z == 3) ? wq : (z == 4) ? wk : wv;
        H = g_WH + (size_t)(z - 3) * 1024 * 512; L = g_WL + (size_t)(z - 3) * 1024 * 512;
        n = 1024 * 512;
    }
    for (int i = blockIdx.x * blockDim.x + threadIdx.x; i < n; i += gridDim.x * blockDim.x) {
        float2 x = ((const float2*)src)[i];
        uint32_t h, l; split2(x.x, x.y, h, l);
        H[i] = h; L[i] = l;
    }
}

// ---------------------------------------------------------------------------
// bf16x3 projection: out = (X @ W^T + bias) * scale, split-stored for attn.
// CTA 128x128, BK=32 (16 kpairs), 2-stage cp.async, 8 warps (warp 32x64).
// Smem planes stride 20 u32 (banks 4g+tig: conflict-free).
// ---------------------------------------------------------------------------
#define PSTR 20
#define PLSZ (128*PSTR)          // 2560 u32 per plane
#define PSTG (4*PLSZ)            // 10240 u32 per stage (AH, AL, BH, BL)
#define PNIT 32

__device__ __forceinline__ void pstage(uint32_t sbase, const uint32_t* __restrict__ XH,
                                       const uint32_t* __restrict__ XL,
                                       const uint32_t* __restrict__ WH,
                                       const uint32_t* __restrict__ WL,
                                       int m0, int n0, int it, int tid)
{
    // per plane: 128 rows x 4 quads = 512 quads; 256 threads -> 2 each
    #pragma unroll
    for (int i = 0; i < 2; i++) {
        int e = tid + i * 256;
        int r = e >> 2, c = e & 3;
        uint32_t o = (uint32_t)(r * PSTR + c * 4) * 4;
        const size_t gi = (size_t)(m0 + r) * 512 + it * 16 + c * 4;
        cp16s(sbase + o,              XH + gi);
        cp16s(sbase + PLSZ*4 + o,     XL + gi);
        const size_t gw = (size_t)(n0 + r) * 512 + it * 16 + c * 4;
        cp16s(sbase + 2*PLSZ*4 + o,   WH + gw);
        cp16s(sbase + 3*PLSZ*4 + o,   WL + gw);
    }
}

__global__ __launch_bounds__(256, 1) void proj_tc(
    const float* __restrict__ Bq, const float* __restrict__ Bk, const float* __restrict__ Bv)
{
    extern __shared__ uint32_t sm[];
    const uint32_t sb = smem_u32(sm);

    const int tid = threadIdx.x;
    const int z = blockIdx.z;
    const uint32_t* XH = g_XH + (size_t)z * 4096 * 512;
    const uint32_t* XL = g_XL + (size_t)z * 4096 * 512;
    const uint32_t* WH = g_WH + (size_t)z * 1024 * 512;
    const uint32_t* WL = g_WL + (size_t)z * 1024 * 512;
    const float* Bi = (z == 0) ? Bq : (z == 1) ? Bk : Bv;
    const float scale = (z == 0) ? 0.125f : 1.0f;

    const int m0 = blockIdx.y * 128;
    const int n0 = blockIdx.x * 128;

    const int warp = tid >> 5, lane = tid & 31;
    const int g = lane >> 2, tig = lane & 3;
    const int wm = warp >> 1, wn = warp & 1;

    float cfr[2][8][4];
    #pragma unroll
    for (int mt = 0; mt < 2; mt++)
        #pragma unroll
        for (int nt = 0; nt < 8; nt++)
            #pragma unroll
            for (int e = 0; e < 4; e++) cfr[mt][nt][e] = 0.f;

    pstage(sb, XH, XL, WH, WL, m0, n0, 0, tid);
    CP_COMMIT();

    for (int it = 0; it < PNIT; it++) {
        if (it + 1 < PNIT)
            pstage(sb + ((it + 1) & 1) * PSTG * 4, XH, XL, WH, WL, m0, n0, it + 1, tid);
        CP_COMMIT();
        CP_WAIT1();
        __syncthreads();

        const uint32_t* AH = sm + (it & 1) * PSTG;
        const uint32_t* AL = AH + PLSZ;
        const uint32_t* BH = AH + 2 * PLSZ;
        const uint32_t* BL = AH + 3 * PLSZ;

        #pragma unroll
        for (int kg = 0; kg < 2; kg++) {
            const int kp1 = kg * 8 + tig, kp2 = kp1 + 4;
            uint32_t ah[2][4], al[2][4];
            #pragma unroll
            for (int mt = 0; mt < 2; mt++) {
                const int r0 = wm * 32 + mt * 16 + g;
                ah[mt][0] = AH[r0*PSTR + kp1]; ah[mt][1] = AH[(r0+8)*PSTR + kp1];
                ah[mt][2] = AH[r0*PSTR + kp2]; ah[mt][3] = AH[(r0+8)*PSTR + kp2];
                al[mt][0] = AL[r0*PSTR + kp1]; al[mt][1] = AL[(r0+8)*PSTR + kp1];
                al[mt][2] = AL[r0*PSTR + kp2]; al[mt][3] = AL[(r0+8)*PSTR + kp2];
            }
            uint32_t bh[8][2], bl[8][2];
            #pragma unroll
            for (int nt = 0; nt < 8; nt++) {
                const int rn = wn * 64 + nt * 8 + g;
                bh[nt][0] = BH[rn*PSTR + kp1]; bh[nt][1] = BH[rn*PSTR + kp2];
                bl[nt][0] = BL[rn*PSTR + kp1]; bl[nt][1] = BL[rn*PSTR + kp2];
            }
            #pragma unroll
            for (int mt = 0; mt < 2; mt++)
                #pragma unroll
                for (int nt = 0; nt < 8; nt++) {
                    mma16(cfr[mt][nt], ah[mt], bl[nt]);
                    mma16(cfr[mt][nt], al[mt], bh[nt]);
                    mma16(cfr[mt][nt], ah[mt], bh[nt]);
                }
        }
        __syncthreads();
    }

    // stage C in smem fp32 [128][132]
    float* Cs = (float*)sm;
    #pragma unroll
    for (int mt = 0; mt < 2; mt++) {
        const int rm = wm * 32 + mt * 16 + g;
        #pragma unroll
        for (int nt = 0; nt < 8; nt++) {
            const int cn = wn * 64 + nt * 8 + 2 * tig;
            Cs[(rm    ) * 132 + cn    ] = cfr[mt][nt][0];
            Cs[(rm    ) * 132 + cn + 1] = cfr[mt][nt][1];
            Cs[(rm + 8) * 132 + cn    ] = cfr[mt][nt][2];
            Cs[(rm + 8) * 132 + cn + 1] = cfr[mt][nt][3];
        }
    }
    __syncthreads();

    if (z < 2) {
        // Q/K: write [(b,h)][s][dp] hi/lo packed
        uint32_t* OH = (z == 0) ? g_QH : g_KH;
        uint32_t* OL = (z == 0) ? g_QL : g_KL;
        const int qcol = (tid & 15) * 4;
        #pragma unroll
        for (int hh = 0; hh < 2; hh++) {
            const int h = ((n0 + hh * 64) >> 6);
            const float4 bv = *(const float4*)(Bi + n0 + hh * 64 + qcol);
            #pragma unroll
            for (int p = 0; p < 8; p++) {
                const int idx = tid + p * 256;
                const int m = idx >> 4;
                const int gm = m0 + m, b = gm >> 10, s = gm & (NS - 1);
                const float* src = Cs + m * 132 + hh * 64 + qcol;
                float v0 = (src[0] + bv.x) * scale;
                float v1 = (src[1] + bv.y) * scale;
                float v2 = (src[2] + bv.z) * scale;
                float v3 = (src[3] + bv.w) * scale;
                uint32_t h0, l0, h1, l1;
                split2(v0, v1, h0, l0);
                split2(v2, v3, h1, l1);
                const size_t o = ((size_t)(b * NH + h) * NS + s) * 32 + (qcol >> 1);
                *(uint2*)(OH + o) = make_uint2(h0, h1);
                *(uint2*)(OL + o) = make_uint2(l0, l1);
            }
        }
    } else {
        // V: transpose-pack over s: [(b,h)][d][sp]
        #pragma unroll 1
        for (int p = 0; p < 32; p++) {
            const int e = tid + p * 256;
            const int sp = e & 63;            // local s-pair
            const int dl = e >> 6;            // 0..127 local n
            const int n = n0 + dl;
            const int h = n >> 6, dd = n & 63;
            const int gm = m0 + 2 * sp;
            const int b = gm >> 10;
            const int spg = (gm & (NS - 1)) >> 1;
            const float bi = Bi[n];
            float v0 = Cs[(2*sp    ) * 132 + dl] + bi;
            float v1 = Cs[(2*sp + 1) * 132 + dl] + bi;
            uint32_t hh, ll;
            split2(v0, v1, hh, ll);
            const size_t o = ((size_t)(b * NH + h) * 64 + dd) * 512 + spg;
            g_VH[o] = hh;
            g_VL[o] = ll;
        }
    }
}

// ---------------------------------------------------------------------------
// bf16x3 flash attention. CTA = (b,h,64-query tile), 4 warps.
// Q fragments preloaded to registers; P repacked from score C-frags in regs
// (no smem staging). Smem planes stride 36 u32 (banks 4g+tig conflict-free).
// ---------------------------------------------------------------------------
#define ASTR 36
#define APL (64*ASTR)    // 2304 u32 per plane

__global__ __launch_bounds__(128) void attn_tc(const float* __restrict__ mask,
                                               float* __restrict__ out)
{
    extern __shared__ uint32_t s[];
    uint32_t* KHs = s;
    uint32_t* KLs = s + APL;
    uint32_t* VHs = s + 2*APL;
    uint32_t* VLs = s + 3*APL;

    const int b = blockIdx.z, h = blockIdx.y;
    const int q0 = blockIdx.x * 64;
    const int tid = threadIdx.x, warp = tid >> 5, lane = tid & 31;
    const int g = lane >> 2, tig = lane & 3;
    const int r0 = warp * 16 + g;

    const size_t bh32 = (size_t)(b * NH + h) * NS * 32;
    const uint32_t* QHg = g_QH + bh32;
    const uint32_t* QLg = g_QL + bh32;
    const uint32_t* KHg = g_KH + bh32;
    const uint32_t* KLg = g_KL + bh32;
    const size_t bhv = (size_t)(b * NH + h) * 64 * 512;
    const uint32_t* VHg = g_VH + bhv;
    const uint32_t* VLg = g_VL + bhv;

    // --- preload Q fragments via smem bounce (K buffers, pre-loop) ---
    #pragma unroll
    for (int i = 0; i < 4; i++) {
        int e = tid + i * 128;
        int r = e >> 3, c = e & 7;
        *(uint4*)(KHs + r*ASTR + c*4) = *(const uint4*)(QHg + (size_t)(q0 + r)*32 + c*4);
        *(uint4*)(KLs + r*ASTR + c*4) = *(const uint4*)(QLg + (size_t)(q0 + r)*32 + c*4);
    }
    __syncthreads();
    uint32_t qh[4][4], ql[4][4];
    #pragma unroll
    for (int kg = 0; kg < 4; kg++) {
        const int kp1 = kg * 8 + tig, kp2 = kp1 + 4;
        qh[kg][0] = KHs[r0*ASTR + kp1]; qh[kg][1] = KHs[(r0+8)*ASTR + kp1];
        qh[kg][2] = KHs[r0*ASTR + kp2]; qh[kg][3] = KHs[(r0+8)*ASTR + kp2];
        ql[kg][0] = KLs[r0*ASTR + kp1]; ql[kg][1] = KLs[(r0+8)*ASTR + kp1];
        ql[kg][2] = KLs[r0*ASTR + kp2]; ql[kg][3] = KLs[(r0+8)*ASTR + kp2];
    }

    float o[8][4];
    #pragma unroll
    for (int nt = 0; nt < 8; nt++)
        #pragma unroll
        for (int e = 0; e < 4; e++) o[nt][e] = 0.f;
    float mrow[2] = {-3.4e38f, -3.4e38f};
    float lsum[2] = {0.f, 0.f};

    for (int jt = 0; jt < NS/64; jt++) {
        const int j0 = jt * 64;
        __syncthreads();
        #pragma unroll
        for (int i = 0; i < 4; i++) {
            int e = tid + i * 128;
            int r = e >> 3, c = e & 7;
            *(uint4*)(KHs + r*ASTR + c*4) = *(const uint4*)(KHg + (size_t)(j0 + r)*32 + c*4);
            *(uint4*)(KLs + r*ASTR + c*4) = *(const uint4*)(KLg + (size_t)(j0 + r)*32 + c*4);
            *(uint4*)(VHs + r*ASTR + c*4) = *(const uint4*)(VHg + (size_t)r*512 + (j0 >> 1) + c*4);
            *(uint4*)(VLs + r*ASTR + c*4) = *(const uint4*)(VLg + (size_t)r*512 + (j0 >> 1) + c*4);
        }
        __syncthreads();

        // ---- scores S[16x64] per warp, bf16x3 ----
        float c[8][4];
        #pragma unroll
        for (int nt = 0; nt < 8; nt++)
            #pragma unroll
            for (int e = 0; e < 4; e++) c[nt][e] = 0.f;

        #pragma unroll
        for (int kg = 0; kg < 4; kg++) {
            const int kp1 = kg * 8 + tig, kp2 = kp1 + 4;
            #pragma unroll
            for (int nt = 0; nt < 8; nt++) {
                const int rn = nt * 8 + g;
                uint32_t bh[2], bl[2];
                bh[0] = KHs[rn*ASTR + kp1]; bh[1] = KHs[rn*ASTR + kp2];
                bl[0] = KLs[rn*ASTR + kp1]; bl[1] = KLs[rn*ASTR + kp2];
                mma16(c[nt], qh[kg], bl);
                mma16(c[nt], ql[kg], bh);
                mma16(c[nt], qh[kg], bh);
            }
        }

        // ---- mask ----
        const float* mr = mask + ((size_t)b*NS + (q0 + r0))*NS + j0 + 2*tig;
        #pragma unroll
        for (int nt = 0; nt < 8; nt++) {
            float2 m0v = *(const float2*)(mr + nt*8);
            float2 m1v = *(const float2*)(mr + (size_t)8*NS + nt*8);
            c[nt][0] = fmaf(m0v.x - 1.f, 1e6f, c[nt][0]);
            c[nt][1] = fmaf(m0v.y - 1.f, 1e6f, c[nt][1]);
            c[nt][2] = fmaf(m1v.x - 1.f, 1e6f, c[nt][2]);
            c[nt][3] = fmaf(m1v.y - 1.f, 1e6f, c[nt][3]);
        }

        // ---- online softmax (rows r0, r0+8; reduce over 4 tig lanes) ----
        #pragma unroll
        for (int sl = 0; sl < 2; sl++) {
            float cm = -3.4e38f;
            #pragma unroll
            for (int nt = 0; nt < 8; nt++)
                cm = fmaxf(cm, fmaxf(c[nt][2*sl], c[nt][2*sl + 1]));
            cm = fmaxf(cm, __shfl_xor_sync(0xffffffffu, cm, 1));
            cm = fmaxf(cm, __shfl_xor_sync(0xffffffffu, cm, 2));
            const float mn = fmaxf(mrow[sl], cm);
            const float alc = __expf(mrow[sl] - mn);
            mrow[sl] = mn;
            float rs = 0.f;
            #pragma unroll
            for (int nt = 0; nt < 8; nt++) {
                c[nt][2*sl]     = __expf(c[nt][2*sl]     - mn);
                c[nt][2*sl + 1] = __expf(c[nt][2*sl + 1] - mn);
                rs += c[nt][2*sl] + c[nt][2*sl + 1];
            }
            rs += __shfl_xor_sync(0xffffffffu, rs, 1);
            rs += __shfl_xor_sync(0xffffffffu, rs, 2);
            lsum[sl] = lsum[sl] * alc + rs;
            #pragma unroll
            for (int nt = 0; nt < 8; nt++) {
                o[nt][2*sl]     *= alc;
                o[nt][2*sl + 1] *= alc;
            }
        }

        // ---- O += P @ V : P A-frags repacked from score C-frags (regs only) ----
        #pragma unroll
        for (int q = 0; q < 4; q++) {
            uint32_t ph[4], pl[4];
            split2(c[2*q    ][0], c[2*q    ][1], ph[0], pl[0]);
            split2(c[2*q    ][2], c[2*q    ][3], ph[1], pl[1]);
            split2(c[2*q + 1][0], c[2*q + 1][1], ph[2], pl[2]);
            split2(c[2*q + 1][2], c[2*q + 1][3], ph[3], pl[3]);
            const int jp1 = q * 8 + tig, jp2 = jp1 + 4;
            #pragma unroll
            for (int nt = 0; nt < 8; nt++) {
                const int rn = nt * 8 + g;
                uint32_t vh[2], vl[2];
                vh[0] = VHs[rn*ASTR + jp1]; vh[1] = VHs[rn*ASTR + jp2];
                vl[0] = VLs[rn*ASTR + jp1]; vl[1] = VLs[rn*ASTR + jp2];
                mma16(o[nt], ph, vl);
                mma16(o[nt], pl, vh);
                mma16(o[nt], ph, vh);
            }
        }
    }

    // ---- epilogue: normalize, write [B, S, H*64] ----
    const float inv0 = 1.0f / lsum[0];
    const float inv1 = 1.0f / lsum[1];
    float* orow = out + ((size_t)b*NS + (q0 + r0))*NE + h*ND + 2*tig;
    #pragma unroll
    for (int nt = 0; nt < 8; nt++) {
        *(float2*)(orow + nt*8) = make_float2(o[nt][0]*inv0, o[nt][1]*inv0);
        *(float2*)(orow + (size_t)8*NE + nt*8) = make_float2(o[nt][2]*inv1, o[nt][3]*inv1);
    }
}

extern "C" void kernel_launch(void* const* d_in, const int* in_sizes, int n_in,
                              void* d_out, int out_size)
{
    const float* query = (const float*)d_in[0];
    const float* key   = (const float*)d_in[1];
    const float* value = (const float*)d_in[2];
    const float* mask  = (const float*)d_in[3];
    const float* Wq    = (const float*)d_in[4];
    const float* bq    = (const float*)d_in[5];
    const float* Wk    = (const float*)d_in[6];
    const float* bk    = (const float*)d_in[7];
    const float* Wv    = (const float*)d_in[8];
    const float* bv    = (const float*)d_in[9];
    float* out = (float*)d_out;

    split_in<<<dim3(512, 6), 256>>>(query, key, value, Wq, Wk, Wv);

    const int proj_smem = 2 * PSTG * 4;   // 81920 B
    cudaFuncSetAttribute(proj_tc, cudaFuncAttributeMaxDynamicSharedMemorySize, proj_smem);
    dim3 pg(NE / 128, (NB * NS) / 128, 3);   // (8, 32, 3)
    proj_tc<<<pg, 256, proj_smem>>>(bq, bk, bv);

    const int attn_smem = 4 * APL * 4;    // 36864 B
    cudaFuncSetAttribute(attn_tc, cudaFuncAttributeMaxDynamicSharedMemorySize, attn_smem);
    dim3 ag(NS/64, NH, NB);
    attn_tc<<<ag, 128, attn_smem>>>(mask, out);
}

// round 8
// speedup vs baseline: 2.1423x; 1.0584x over previous
#include <cuda_runtime.h>
#include <cstdint>
#include <math.h>

#define NB 4
#define NH 16
#define NS 1024
#define ND 64
#define NE 1024

// ---------------------------------------------------------------------------
// Global scratch: bf16 hi/lo packed planes (u32 = 2 bf16, consecutive k).
// ---------------------------------------------------------------------------
__device__ uint32_t g_XH[3 * 4096 * 512];   // inputs  [z][m][kp]
__device__ uint32_t g_XL[3 * 4096 * 512];
__device__ uint32_t g_WH[3 * 1024 * 512];   // weights [z][n][kp]
__device__ uint32_t g_WL[3 * 1024 * 512];
__device__ uint32_t g_QH[NB*NH*NS*32];      // Q/K: [(b,h)][s][dp]
__device__ uint32_t g_QL[NB*NH*NS*32];
__device__ uint32_t g_KH[NB*NH*NS*32];
__device__ uint32_t g_KL[NB*NH*NS*32];
__device__ uint32_t g_VH[NB*NH*64*512];     // V: [(b,h)][d][sp]  (key-pair packed)
__device__ uint32_t g_VL[NB*NH*64*512];

// ---------------------------------------------------------------------------
// helpers
// ---------------------------------------------------------------------------
__device__ __forceinline__ uint32_t smem_u32(const void* p) {
    uint32_t a;
    asm("{ .reg .u64 t; cvta.to.shared.u64 t, %1; cvt.u32.u64 %0, t; }" : "=r"(a) : "l"(p));
    return a;
}
__device__ __forceinline__ void cp16s(uint32_t dst, const void* src) {
    asm volatile("cp.async.cg.shared.global [%0], [%1], 16;" :: "r"(dst), "l"(src));
}
#define CP_COMMIT() asm volatile("cp.async.commit_group;" ::: "memory")
#define CP_WAIT1()  asm volatile("cp.async.wait_group 1;"  ::: "memory")

// pack two fp32 into bf16x2 (lo_elem -> bits[15:0], hi_elem -> bits[31:16])
__device__ __forceinline__ uint32_t packbf(float e0, float e1) {
    uint32_t r; asm("cvt.rn.bf16x2.f32 %0, %1, %2;" : "=r"(r) : "f"(e1), "f"(e0)); return r;
}
// split pair into hi plane + lo (residual) plane
__device__ __forceinline__ void split2(float x0, float x1, uint32_t& h, uint32_t& l) {
    h = packbf(x0, x1);
    float h0 = __uint_as_float(h << 16);
    float h1 = __uint_as_float(h & 0xffff0000u);
    l = packbf(x0 - h0, x1 - h1);
}

// bf16 m16n8k16 mma.sync
__device__ __forceinline__ void mma16(float* d, const uint32_t* a, const uint32_t* b) {
    asm volatile(
        "mma.sync.aligned.m16n8k16.row.col.f32.bf16.bf16.f32 "
        "{%0,%1,%2,%3}, {%4,%5,%6,%7}, {%8,%9}, {%0,%1,%2,%3};"
        : "+f"(d[0]), "+f"(d[1]), "+f"(d[2]), "+f"(d[3])
        : "r"(a[0]), "r"(a[1]), "r"(a[2]), "r"(a[3]), "r"(b[0]), "r"(b[1]));
}

// ---------------------------------------------------------------------------
// Pre-pass: split 6 fp32 tensors into bf16 hi/lo packed planes.
// ---------------------------------------------------------------------------
__global__ void split_in(const float* __restrict__ q, const float* __restrict__ k,
                         const float* __restrict__ v, const float* __restrict__ wq,
                         const float* __restrict__ wk, const float* __restrict__ wv)
{
    const int z = blockIdx.y;
    const float* src; uint32_t* H; uint32_t* L; int n;
    if (z < 3) {
        src = (z == 0) ? q : (z == 1) ? k : v;
        H = g_XH + (size_t)z * 4096 * 512; L = g_XL + (size_t)z * 4096 * 512;
        n = 4096 * 512;
    } else {
        src = (z == 3) ? wq : (z == 4) ? wk : wv;
        H = g_WH + (size_t)(z - 3) * 1024 * 512; L = g_WL + (size_t)(z - 3) * 1024 * 512;
        n = 1024 * 512;
    }
    for (int i = blockIdx.x * blockDim.x + threadIdx.x; i < n; i += gridDim.x * blockDim.x) {
        float2 x = ((const float2*)src)[i];
        uint32_t h, l; split2(x.x, x.y, h, l);
        H[i] = h; L[i] = l;
    }
}

// ---------------------------------------------------------------------------
// bf16x3 projection (unchanged from R7, validated).
// ---------------------------------------------------------------------------
#define PSTR 20
#define PLSZ (128*PSTR)
#define PSTG (4*PLSZ)
#define PNIT 32

__device__ __forceinline__ void pstage(uint32_t sbase, const uint32_t* __restrict__ XH,
                                       const uint32_t* __restrict__ XL,
                                       const uint32_t* __restrict__ WH,
                                       const uint32_t* __restrict__ WL,
                                       int m0, int n0, int it, int tid)
{
    #pragma unroll
    for (int i = 0; i < 2; i++) {
        int e = tid + i * 256;
        int r = e >> 2, c = e & 3;
        uint32_t o = (uint32_t)(r * PSTR + c * 4) * 4;
        const size_t gi = (size_t)(m0 + r) * 512 + it * 16 + c * 4;
        cp16s(sbase + o,              XH + gi);
        cp16s(sbase + PLSZ*4 + o,     XL + gi);
        const size_t gw = (size_t)(n0 + r) * 512 + it * 16 + c * 4;
        cp16s(sbase + 2*PLSZ*4 + o,   WH + gw);
        cp16s(sbase + 3*PLSZ*4 + o,   WL + gw);
    }
}

__global__ __launch_bounds__(256, 1) void proj_tc(
    const float* __restrict__ Bq, const float* __restrict__ Bk, const float* __restrict__ Bv)
{
    extern __shared__ uint32_t sm[];
    const uint32_t sb = smem_u32(sm);

    const int tid = threadIdx.x;
    const int z = blockIdx.z;
    const uint32_t* XH = g_XH + (size_t)z * 4096 * 512;
    const uint32_t* XL = g_XL + (size_t)z * 4096 * 512;
    const uint32_t* WH = g_WH + (size_t)z * 1024 * 512;
    const uint32_t* WL = g_WL + (size_t)z * 1024 * 512;
    const float* Bi = (z == 0) ? Bq : (z == 1) ? Bk : Bv;
    const float scale = (z == 0) ? 0.125f : 1.0f;

    const int m0 = blockIdx.y * 128;
    const int n0 = blockIdx.x * 128;

    const int warp = tid >> 5, lane = tid & 31;
    const int g = lane >> 2, tig = lane & 3;
    const int wm = warp >> 1, wn = warp & 1;

    float cfr[2][8][4];
    #pragma unroll
    for (int mt = 0; mt < 2; mt++)
        #pragma unroll
        for (int nt = 0; nt < 8; nt++)
            #pragma unroll
            for (int e = 0; e < 4; e++) cfr[mt][nt][e] = 0.f;

    pstage(sb, XH, XL, WH, WL, m0, n0, 0, tid);
    CP_COMMIT();

    for (int it = 0; it < PNIT; it++) {
        if (it + 1 < PNIT)
            pstage(sb + ((it + 1) & 1) * PSTG * 4, XH, XL, WH, WL, m0, n0, it + 1, tid);
        CP_COMMIT();
        CP_WAIT1();
        __syncthreads();

        const uint32_t* AH = sm + (it & 1) * PSTG;
        const uint32_t* AL = AH + PLSZ;
        const uint32_t* BH = AH + 2 * PLSZ;
        const uint32_t* BL = AH + 3 * PLSZ;

        #pragma unroll
        for (int kg = 0; kg < 2; kg++) {
            const int kp1 = kg * 8 + tig, kp2 = kp1 + 4;
            uint32_t ah[2][4], al[2][4];
            #pragma unroll
            for (int mt = 0; mt < 2; mt++) {
                const int r0 = wm * 32 + mt * 16 + g;
                ah[mt][0] = AH[r0*PSTR + kp1]; ah[mt][1] = AH[(r0+8)*PSTR + kp1];
                ah[mt][2] = AH[r0*PSTR + kp2]; ah[mt][3] = AH[(r0+8)*PSTR + kp2];
                al[mt][0] = AL[r0*PSTR + kp1]; al[mt][1] = AL[(r0+8)*PSTR + kp1];
                al[mt][2] = AL[r0*PSTR + kp2]; al[mt][3] = AL[(r0+8)*PSTR + kp2];
            }
            uint32_t bh[8][2], bl[8][2];
            #pragma unroll
            for (int nt = 0; nt < 8; nt++) {
                const int rn = wn * 64 + nt * 8 + g;
                bh[nt][0] = BH[rn*PSTR + kp1]; bh[nt][1] = BH[rn*PSTR + kp2];
                bl[nt][0] = BL[rn*PSTR + kp1]; bl[nt][1] = BL[rn*PSTR + kp2];
            }
            #pragma unroll
            for (int mt = 0; mt < 2; mt++)
                #pragma unroll
                for (int nt = 0; nt < 8; nt++) {
                    mma16(cfr[mt][nt], ah[mt], bl[nt]);
                    mma16(cfr[mt][nt], al[mt], bh[nt]);
                    mma16(cfr[mt][nt], ah[mt], bh[nt]);
                }
        }
        __syncthreads();
    }

    float* Cs = (float*)sm;
    #pragma unroll
    for (int mt = 0; mt < 2; mt++) {
        const int rm = wm * 32 + mt * 16 + g;
        #pragma unroll
        for (int nt = 0; nt < 8; nt++) {
            const int cn = wn * 64 + nt * 8 + 2 * tig;
            Cs[(rm    ) * 132 + cn    ] = cfr[mt][nt][0];
            Cs[(rm    ) * 132 + cn + 1] = cfr[mt][nt][1];
            Cs[(rm + 8) * 132 + cn    ] = cfr[mt][nt][2];
            Cs[(rm + 8) * 132 + cn + 1] = cfr[mt][nt][3];
        }
    }
    __syncthreads();

    if (z < 2) {
        uint32_t* OH = (z == 0) ? g_QH : g_KH;
        uint32_t* OL = (z == 0) ? g_QL : g_KL;
        const int qcol = (tid & 15) * 4;
        #pragma unroll
        for (int hh = 0; hh < 2; hh++) {
            const int h = ((n0 + hh * 64) >> 6);
            const float4 bv = *(const float4*)(Bi + n0 + hh * 64 + qcol);
            #pragma unroll
            for (int p = 0; p < 8; p++) {
                const int idx = tid + p * 256;
                const int m = idx >> 4;
                const int gm = m0 + m, b = gm >> 10, s = gm & (NS - 1);
                const float* src = Cs + m * 132 + hh * 64 + qcol;
                float v0 = (src[0] + bv.x) * scale;
                float v1 = (src[1] + bv.y) * scale;
                float v2 = (src[2] + bv.z) * scale;
                float v3 = (src[3] + bv.w) * scale;
                uint32_t h0, l0, h1, l1;
                split2(v0, v1, h0, l0);
                split2(v2, v3, h1, l1);
                const size_t o = ((size_t)(b * NH + h) * NS + s) * 32 + (qcol >> 1);
                *(uint2*)(OH + o) = make_uint2(h0, h1);
                *(uint2*)(OL + o) = make_uint2(l0, l1);
            }
        }
    } else {
        #pragma unroll 1
        for (int p = 0; p < 32; p++) {
            const int e = tid + p * 256;
            const int sp = e & 63;
            const int dl = e >> 6;
            const int n = n0 + dl;
            const int h = n >> 6, dd = n & 63;
            const int gm = m0 + 2 * sp;
            const int b = gm >> 10;
            const int spg = (gm & (NS - 1)) >> 1;
            const float bi = Bi[n];
            float v0 = Cs[(2*sp    ) * 132 + dl] + bi;
            float v1 = Cs[(2*sp + 1) * 132 + dl] + bi;
            uint32_t hh, ll;
            split2(v0, v1, hh, ll);
            const size_t o = ((size_t)(b * NH + h) * 64 + dd) * 512 + spg;
            g_VH[o] = hh;
            g_VL[o] = ll;
        }
    }
}

// ---------------------------------------------------------------------------
// bf16x3 flash attention, v2: CTA = (b,h,128-query tile), 8 warps (256 thr),
// cp.async double-buffered K/V tiles (2 stages x 4 planes). Q fragments in
// registers; P repacked from score C-frags in regs. Stride 36 conflict-free.
// ---------------------------------------------------------------------------
#define ASTR 36
#define APL (64*ASTR)    // 2304 u32 per plane
#define ASTG (4*APL)     // 9216 u32 per stage

__device__ __forceinline__ void aload(uint32_t sb, int stage, int j0,
                                      const uint32_t* __restrict__ KHg,
                                      const uint32_t* __restrict__ KLg,
                                      const uint32_t* __restrict__ VHg,
                                      const uint32_t* __restrict__ VLg, int tid)
{
    const uint32_t base = sb + (uint32_t)stage * ASTG * 4;
    // K planes: 512 quads each; 256 threads -> 2 per plane
    #pragma unroll
    for (int i = 0; i < 2; i++) {
        int e = tid + i * 256;
        int r = e >> 3, c = e & 7;
        uint32_t o = (uint32_t)(r * ASTR + c * 4) * 4;
        const size_t gk = (size_t)(j0 + r) * 32 + c * 4;
        cp16s(base + o,            KHg + gk);
        cp16s(base + APL*4 + o,    KLg + gk);
        const size_t gv = (size_t)r * 512 + (j0 >> 1) + c * 4;
        cp16s(base + 2*APL*4 + o,  VHg + gv);
        cp16s(base + 3*APL*4 + o,  VLg + gv);
    }
}

__global__ __launch_bounds__(256) void attn_tc(const float* __restrict__ mask,
                                               float* __restrict__ out)
{
    extern __shared__ uint32_t s[];
    const uint32_t sb = smem_u32(s);

    const int b = blockIdx.z, h = blockIdx.y;
    const int q0 = blockIdx.x * 128;
    const int tid = threadIdx.x, warp = tid >> 5, lane = tid & 31;
    const int g = lane >> 2, tig = lane & 3;
    const int r0 = warp * 16 + g;            // 0..127

    const size_t bh32 = (size_t)(b * NH + h) * NS * 32;
    const uint32_t* QHg = g_QH + bh32;
    const uint32_t* QLg = g_QL + bh32;
    const uint32_t* KHg = g_KH + bh32;
    const uint32_t* KLg = g_KL + bh32;
    const size_t bhv = (size_t)(b * NH + h) * 64 * 512;
    const uint32_t* VHg = g_VH + bhv;
    const uint32_t* VLg = g_VL + bhv;

    // --- Q bounce through both stages' KH/KL planes: vr<64 -> stage0, else 1
    #pragma unroll
    for (int i = 0; i < 4; i++) {
        int e = tid + i * 256;               // 0..1023
        int vr = e >> 3, c = e & 7;
        uint32_t idx = (uint32_t)(vr >> 6) * ASTG + (uint32_t)(vr & 63) * ASTR + c * 4;
        *(uint4*)(s + idx)       = *(const uint4*)(QHg + (size_t)(q0 + vr) * 32 + c * 4);
        *(uint4*)(s + idx + APL) = *(const uint4*)(QLg + (size_t)(q0 + vr) * 32 + c * 4);
    }
    __syncthreads();
    uint32_t qh[4][4], ql[4][4];
    {
        const uint32_t qbase = (uint32_t)(r0 >> 6) * ASTG;
        const int lr = r0 & 63;
        #pragma unroll
        for (int kg = 0; kg < 4; kg++) {
            const int kp1 = kg * 8 + tig, kp2 = kp1 + 4;
            qh[kg][0] = s[qbase + lr*ASTR + kp1]; qh[kg][1] = s[qbase + (lr+8)*ASTR + kp1];
            qh[kg][2] = s[qbase + lr*ASTR + kp2]; qh[kg][3] = s[qbase + (lr+8)*ASTR + kp2];
            ql[kg][0] = s[qbase + APL + lr*ASTR + kp1]; ql[kg][1] = s[qbase + APL + (lr+8)*ASTR + kp1];
            ql[kg][2] = s[qbase + APL + lr*ASTR + kp2]; ql[kg][3] = s[qbase + APL + (lr+8)*ASTR + kp2];
        }
    }
    __syncthreads();                         // done reading Q from stage buffers

    float o[8][4];
    #pragma unroll
    for (int nt = 0; nt < 8; nt++)
        #pragma unroll
        for (int e = 0; e < 4; e++) o[nt][e] = 0.f;
    float mrow[2] = {-3.4e38f, -3.4e38f};
    float lsum[2] = {0.f, 0.f};

    aload(sb, 0, 0, KHg, KLg, VHg, VLg, tid);
    CP_COMMIT();

    for (int jt = 0; jt < NS/64; jt++) {
        if (jt + 1 < NS/64)
            aload(sb, (jt + 1) & 1, (jt + 1) * 64, KHg, KLg, VHg, VLg, tid);
        CP_COMMIT();
        CP_WAIT1();
        __syncthreads();

        const uint32_t* KHs = s + (jt & 1) * ASTG;
        const uint32_t* KLs = KHs + APL;
        const uint32_t* VHs = KHs + 2*APL;
        const uint32_t* VLs = KHs + 3*APL;
        const int j0 = jt * 64;

        // ---- scores S[16x64] per warp, bf16x3 ----
        float c[8][4];
        #pragma unroll
        for (int nt = 0; nt < 8; nt++)
            #pragma unroll
            for (int e = 0; e < 4; e++) c[nt][e] = 0.f;

        #pragma unroll
        for (int kg = 0; kg < 4; kg++) {
            const int kp1 = kg * 8 + tig, kp2 = kp1 + 4;
            #pragma unroll
            for (int nt = 0; nt < 8; nt++) {
                const int rn = nt * 8 + g;
                uint32_t bh[2], bl[2];
                bh[0] = KHs[rn*ASTR + kp1]; bh[1] = KHs[rn*ASTR + kp2];
                bl[0] = KLs[rn*ASTR + kp1]; bl[1] = KLs[rn*ASTR + kp2];
                mma16(c[nt], qh[kg], bl);
                mma16(c[nt], ql[kg], bh);
                mma16(c[nt], qh[kg], bh);
            }
        }

        // ---- mask ----
        const float* mr = mask + ((size_t)b*NS + (q0 + r0))*NS + j0 + 2*tig;
        #pragma unroll
        for (int nt = 0; nt < 8; nt++) {
            float2 m0v = *(const float2*)(mr + nt*8);
            float2 m1v = *(const float2*)(mr + (size_t)8*NS + nt*8);
            c[nt][0] = fmaf(m0v.x - 1.f, 1e6f, c[nt][0]);
            c[nt][1] = fmaf(m0v.y - 1.f, 1e6f, c[nt][1]);
            c[nt][2] = fmaf(m1v.x - 1.f, 1e6f, c[nt][2]);
            c[nt][3] = fmaf(m1v.y - 1.f, 1e6f, c[nt][3]);
        }

        // ---- online softmax (rows r0, r0+8; reduce over 4 tig lanes) ----
        #pragma unroll
        for (int sl = 0; sl < 2; sl++) {
            float cm = -3.4e38f;
            #pragma unroll
            for (int nt = 0; nt < 8; nt++)
                cm = fmaxf(cm, fmaxf(c[nt][2*sl], c[nt][2*sl + 1]));
            cm = fmaxf(cm, __shfl_xor_sync(0xffffffffu, cm, 1));
            cm = fmaxf(cm, __shfl_xor_sync(0xffffffffu, cm, 2));
            const float mn = fmaxf(mrow[sl], cm);
            const float alc = __expf(mrow[sl] - mn);
            mrow[sl] = mn;
            float rs = 0.f;
            #pragma unroll
            for (int nt = 0; nt < 8; nt++) {
                c[nt][2*sl]     = __expf(c[nt][2*sl]     - mn);
                c[nt][2*sl + 1] = __expf(c[nt][2*sl + 1] - mn);
                rs += c[nt][2*sl] + c[nt][2*sl + 1];
            }
            rs += __shfl_xor_sync(0xffffffffu, rs, 1);
            rs += __shfl_xor_sync(0xffffffffu, rs, 2);
            lsum[sl] = lsum[sl] * alc + rs;
            #pragma unroll
            for (int nt = 0; nt < 8; nt++) {
                o[nt][2*sl]     *= alc;
                o[nt][2*sl + 1] *= alc;
            }
        }

        // ---- O += P @ V : P A-frags repacked from score C-frags (regs only) ----
        #pragma unroll
        for (int q = 0; q < 4; q++) {
            uint32_t ph[4], pl[4];
            split2(c[2*q    ][0], c[2*q    ][1], ph[0], pl[0]);
            split2(c[2*q    ][2], c[2*q    ][3], ph[1], pl[1]);
            split2(c[2*q + 1][0], c[2*q + 1][1], ph[2], pl[2]);
            split2(c[2*q + 1][2], c[2*q + 1][3], ph[3], pl[3]);
            const int jp1 = q * 8 + tig, jp2 = jp1 + 4;
            #pragma unroll
            for (int nt = 0; nt < 8; nt++) {
                const int rn = nt * 8 + g;
                uint32_t vh[2], vl[2];
                vh[0] = VHs[rn*ASTR + jp1]; vh[1] = VHs[rn*ASTR + jp2];
                vl[0] = VLs[rn*ASTR + jp1]; vl[1] = VLs[rn*ASTR + jp2];
                mma16(o[nt], ph, vl);
                mma16(o[nt], pl, vh);
                mma16(o[nt], ph, vh);
            }
        }
        __syncthreads();                     // compute done; stage reusable
    }

    // ---- epilogue: normalize, write [B, S, H*64] ----
    const float inv0 = 1.0f / lsum[0];
    const float inv1 = 1.0f / lsum[1];
    float* orow = out + ((size_t)b*NS + (q0 + r0))*NE + h*ND + 2*tig;
    #pragma unroll
    for (int nt = 0; nt < 8; nt++) {
        *(float2*)(orow + nt*8) = make_float2(o[nt][0]*inv0, o[nt][1]*inv0);
        *(float2*)(orow + (size_t)8*NE + nt*8) = make_float2(o[nt][2]*inv1, o[nt][3]*inv1);
    }
}

extern "C" void kernel_launch(void* const* d_in, const int* in_sizes, int n_in,
                              void* d_out, int out_size)
{
    const float* query = (const float*)d_in[0];
    const float* key   = (const float*)d_in[1];
    const float* value = (const float*)d_in[2];
    const float* mask  = (const float*)d_in[3];
    const float* Wq    = (const float*)d_in[4];
    const float* bq    = (const float*)d_in[5];
    const float* Wk    = (const float*)d_in[6];
    const float* bk    = (const float*)d_in[7];
    const float* Wv    = (const float*)d_in[8];
    const float* bv    = (const float*)d_in[9];
    float* out = (float*)d_out;

    split_in<<<dim3(512, 6), 256>>>(query, key, value, Wq, Wk, Wv);

    const int proj_smem = 2 * PSTG * 4;   // 81920 B
    cudaFuncSetAttribute(proj_tc, cudaFuncAttributeMaxDynamicSharedMemorySize, proj_smem);
    dim3 pg(NE / 128, (NB * NS) / 128, 3);   // (8, 32, 3)
    proj_tc<<<pg, 256, proj_smem>>>(bq, bk, bv);

    const int attn_smem = 2 * ASTG * 4;   // 73728 B
    cudaFuncSetAttribute(attn_tc, cudaFuncAttributeMaxDynamicSharedMemorySize, attn_smem);
    dim3 ag(NS/128, NH, NB);              // (8, 16, 4) = 512 CTAs
    attn_tc<<<ag, 256, attn_smem>>>(mask, out);
}

// round 9
// speedup vs baseline: 2.3782x; 1.1101x over previous
#include <cuda_runtime.h>
#include <cstdint>
#include <math.h>

#define NB 4
#define NH 16
#define NS 1024
#define ND 64
#define NE 1024

// ---------------------------------------------------------------------------
// Global scratch: bf16 hi/lo packed planes (u32 = 2 bf16, consecutive k).
// ---------------------------------------------------------------------------
__device__ uint32_t g_XH[3 * 4096 * 512];   // inputs  [z][m][kp]
__device__ uint32_t g_XL[3 * 4096 * 512];
__device__ uint32_t g_WH[3 * 1024 * 512];   // weights [z][n][kp]
__device__ uint32_t g_WL[3 * 1024 * 512];
__device__ uint32_t g_QH[NB*NH*NS*32];      // Q/K: [(b,h)][s][dp]
__device__ uint32_t g_QL[NB*NH*NS*32];
__device__ uint32_t g_KH[NB*NH*NS*32];
__device__ uint32_t g_KL[NB*NH*NS*32];
__device__ uint32_t g_VH[NB*NH*64*512];     // V: [(b,h)][d][sp]  (key-pair packed)
__device__ uint32_t g_VL[NB*NH*64*512];

// ---------------------------------------------------------------------------
// helpers
// ---------------------------------------------------------------------------
__device__ __forceinline__ uint32_t smem_u32(const void* p) {
    uint32_t a;
    asm("{ .reg .u64 t; cvta.to.shared.u64 t, %1; cvt.u32.u64 %0, t; }" : "=r"(a) : "l"(p));
    return a;
}
__device__ __forceinline__ void cp16s(uint32_t dst, const void* src) {
    asm volatile("cp.async.cg.shared.global [%0], [%1], 16;" :: "r"(dst), "l"(src));
}
#define CP_COMMIT() asm volatile("cp.async.commit_group;" ::: "memory")
#define CP_WAIT1()  asm volatile("cp.async.wait_group 1;"  ::: "memory")

__device__ __forceinline__ uint32_t packbf(float e0, float e1) {
    uint32_t r; asm("cvt.rn.bf16x2.f32 %0, %1, %2;" : "=r"(r) : "f"(e1), "f"(e0)); return r;
}
__device__ __forceinline__ void split2(float x0, float x1, uint32_t& h, uint32_t& l) {
    h = packbf(x0, x1);
    float h0 = __uint_as_float(h << 16);
    float h1 = __uint_as_float(h & 0xffff0000u);
    l = packbf(x0 - h0, x1 - h1);
}

// bf16 m16n8k16 mma.sync
__device__ __forceinline__ void mma16(float* d, const uint32_t* a, const uint32_t* b) {
    asm volatile(
        "mma.sync.aligned.m16n8k16.row.col.f32.bf16.bf16.f32 "
        "{%0,%1,%2,%3}, {%4,%5,%6,%7}, {%8,%9}, {%0,%1,%2,%3};"
        : "+f"(d[0]), "+f"(d[1]), "+f"(d[2]), "+f"(d[3])
        : "r"(a[0]), "r"(a[1]), "r"(a[2]), "r"(a[3]), "r"(b[0]), "r"(b[1]));
}

// ldmatrix x4: 4 fragment regs in one instruction
__device__ __forceinline__ void ldsm4(uint32_t* r, uint32_t addr) {
    asm volatile("ldmatrix.sync.aligned.m8n8.x4.shared.b16 {%0,%1,%2,%3}, [%4];"
        : "=r"(r[0]), "=r"(r[1]), "=r"(r[2]), "=r"(r[3]) : "r"(addr));
}

// ---------------------------------------------------------------------------
// Pre-pass: split 6 fp32 tensors into bf16 hi/lo packed planes.
// ---------------------------------------------------------------------------
__global__ void split_in(const float* __restrict__ q, const float* __restrict__ k,
                         const float* __restrict__ v, const float* __restrict__ wq,
                         const float* __restrict__ wk, const float* __restrict__ wv)
{
    const int z = blockIdx.y;
    const float* src; uint32_t* H; uint32_t* L; int n;
    if (z < 3) {
        src = (z == 0) ? q : (z == 1) ? k : v;
        H = g_XH + (size_t)z * 4096 * 512; L = g_XL + (size_t)z * 4096 * 512;
        n = 4096 * 512;
    } else {
        src = (z == 3) ? wq : (z == 4) ? wk : wv;
        H = g_WH + (size_t)(z - 3) * 1024 * 512; L = g_WL + (size_t)(z - 3) * 1024 * 512;
        n = 1024 * 512;
    }
    for (int i = blockIdx.x * blockDim.x + threadIdx.x; i < n; i += gridDim.x * blockDim.x) {
        float2 x = ((const float2*)src)[i];
        uint32_t h, l; split2(x.x, x.y, h, l);
        H[i] = h; L[i] = l;
    }
}

// ---------------------------------------------------------------------------
// bf16x3 projection, v2: ldmatrix fragment loads, 2 CTAs/SM.
// ---------------------------------------------------------------------------
#define PSTR 20
#define PLSZ (128*PSTR)
#define PSTG (4*PLSZ)
#define PNIT 32

__device__ __forceinline__ void pstage(uint32_t sbase, const uint32_t* __restrict__ XH,
                                       const uint32_t* __restrict__ XL,
                                       const uint32_t* __restrict__ WH,
                                       const uint32_t* __restrict__ WL,
                                       int m0, int n0, int it, int tid)
{
    #pragma unroll
    for (int i = 0; i < 2; i++) {
        int e = tid + i * 256;
        int r = e >> 2, c = e & 3;
        uint32_t o = (uint32_t)(r * PSTR + c * 4) * 4;
        const size_t gi = (size_t)(m0 + r) * 512 + it * 16 + c * 4;
        cp16s(sbase + o,              XH + gi);
        cp16s(sbase + PLSZ*4 + o,     XL + gi);
        const size_t gw = (size_t)(n0 + r) * 512 + it * 16 + c * 4;
        cp16s(sbase + 2*PLSZ*4 + o,   WH + gw);
        cp16s(sbase + 3*PLSZ*4 + o,   WL + gw);
    }
}

__global__ __launch_bounds__(256, 2) void proj_tc(
    const float* __restrict__ Bq, const float* __restrict__ Bk, const float* __restrict__ Bv)
{
    extern __shared__ uint32_t sm[];
    const uint32_t sb = smem_u32(sm);

    const int tid = threadIdx.x;
    const int z = blockIdx.z;
    const uint32_t* XH = g_XH + (size_t)z * 4096 * 512;
    const uint32_t* XL = g_XL + (size_t)z * 4096 * 512;
    const uint32_t* WH = g_WH + (size_t)z * 1024 * 512;
    const uint32_t* WL = g_WL + (size_t)z * 1024 * 512;
    const float* Bi = (z == 0) ? Bq : (z == 1) ? Bk : Bv;
    const float scale = (z == 0) ? 0.125f : 1.0f;

    const int m0 = blockIdx.y * 128;
    const int n0 = blockIdx.x * 128;

    const int warp = tid >> 5, lane = tid & 31;
    const int g = lane >> 2, tig = lane & 3;
    const int wm = warp >> 1, wn = warp & 1;
    const int mid = lane >> 3, lr = lane & 7;
    // ldmatrix per-lane row/col offsets
    const int arowl = (mid & 1) * 8 + lr, acol = (mid >> 1) * 4;   // A frags
    const int browl = (mid >> 1) * 8 + lr, bcol = (mid & 1) * 4;   // B frags

    float cfr[2][8][4];
    #pragma unroll
    for (int mt = 0; mt < 2; mt++)
        #pragma unroll
        for (int nt = 0; nt < 8; nt++)
            #pragma unroll
            for (int e = 0; e < 4; e++) cfr[mt][nt][e] = 0.f;

    pstage(sb, XH, XL, WH, WL, m0, n0, 0, tid);
    CP_COMMIT();

    for (int it = 0; it < PNIT; it++) {
        if (it + 1 < PNIT)
            pstage(sb + ((it + 1) & 1) * PSTG * 4, XH, XL, WH, WL, m0, n0, it + 1, tid);
        CP_COMMIT();
        CP_WAIT1();
        __syncthreads();

        const uint32_t AHb = sb + ((it & 1) * PSTG) * 4;
        const uint32_t ALb = AHb + PLSZ * 4;
        const uint32_t BHb = AHb + 2 * PLSZ * 4;
        const uint32_t BLb = AHb + 3 * PLSZ * 4;

        #pragma unroll
        for (int kg = 0; kg < 2; kg++) {
            const int kgb = kg * 8;
            uint32_t ah[2][4], al[2][4];
            #pragma unroll
            for (int mt = 0; mt < 2; mt++) {
                const uint32_t oa = (uint32_t)((wm*32 + mt*16 + arowl) * PSTR + kgb + acol) * 4;
                ldsm4(ah[mt], AHb + oa);
                ldsm4(al[mt], ALb + oa);
            }
            #pragma unroll
            for (int np = 0; np < 4; np++) {
                const int nt0 = 2 * np;
                const uint32_t ob = (uint32_t)((wn*64 + nt0*8 + browl) * PSTR + kgb + bcol) * 4;
                uint32_t bh[4], bl[4];
                ldsm4(bh, BHb + ob);
                ldsm4(bl, BLb + ob);
                #pragma unroll
                for (int mt = 0; mt < 2; mt++) {
                    mma16(cfr[mt][nt0],   ah[mt], bl);
                    mma16(cfr[mt][nt0],   al[mt], bh);
                    mma16(cfr[mt][nt0],   ah[mt], bh);
                    mma16(cfr[mt][nt0+1], ah[mt], bl + 2);
                    mma16(cfr[mt][nt0+1], al[mt], bh + 2);
                    mma16(cfr[mt][nt0+1], ah[mt], bh + 2);
                }
            }
        }
        __syncthreads();
    }

    float* Cs = (float*)sm;
    #pragma unroll
    for (int mt = 0; mt < 2; mt++) {
        const int rm = wm * 32 + mt * 16 + g;
        #pragma unroll
        for (int nt = 0; nt < 8; nt++) {
            const int cn = wn * 64 + nt * 8 + 2 * tig;
            Cs[(rm    ) * 132 + cn    ] = cfr[mt][nt][0];
            Cs[(rm    ) * 132 + cn + 1] = cfr[mt][nt][1];
            Cs[(rm + 8) * 132 + cn    ] = cfr[mt][nt][2];
            Cs[(rm + 8) * 132 + cn + 1] = cfr[mt][nt][3];
        }
    }
    __syncthreads();

    if (z < 2) {
        uint32_t* OH = (z == 0) ? g_QH : g_KH;
        uint32_t* OL = (z == 0) ? g_QL : g_KL;
        const int qcol = (tid & 15) * 4;
        #pragma unroll
        for (int hh = 0; hh < 2; hh++) {
            const int h = ((n0 + hh * 64) >> 6);
            const float4 bv = *(const float4*)(Bi + n0 + hh * 64 + qcol);
            #pragma unroll
            for (int p = 0; p < 8; p++) {
                const int idx = tid + p * 256;
                const int m = idx >> 4;
                const int gm = m0 + m, b = gm >> 10, s = gm & (NS - 1);
                const float* src = Cs + m * 132 + hh * 64 + qcol;
                float v0 = (src[0] + bv.x) * scale;
                float v1 = (src[1] + bv.y) * scale;
                float v2 = (src[2] + bv.z) * scale;
                float v3 = (src[3] + bv.w) * scale;
                uint32_t h0, l0, h1, l1;
                split2(v0, v1, h0, l0);
                split2(v2, v3, h1, l1);
                const size_t o = ((size_t)(b * NH + h) * NS + s) * 32 + (qcol >> 1);
                *(uint2*)(OH + o) = make_uint2(h0, h1);
                *(uint2*)(OL + o) = make_uint2(l0, l1);
            }
        }
    } else {
        #pragma unroll 1
        for (int p = 0; p < 32; p++) {
            const int e = tid + p * 256;
            const int sp = e & 63;
            const int dl = e >> 6;
            const int n = n0 + dl;
            const int h = n >> 6, dd = n & 63;
            const int gm = m0 + 2 * sp;
            const int b = gm >> 10;
            const int spg = (gm & (NS - 1)) >> 1;
            const float bi = Bi[n];
            float v0 = Cs[(2*sp    ) * 132 + dl] + bi;
            float v1 = Cs[(2*sp + 1) * 132 + dl] + bi;
            uint32_t hh, ll;
            split2(v0, v1, hh, ll);
            const size_t o = ((size_t)(b * NH + h) * 64 + dd) * 512 + spg;
            g_VH[o] = hh;
            g_VL[o] = ll;
        }
    }
}

// ---------------------------------------------------------------------------
// bf16x3 flash attention, v3: ldmatrix K/V frag loads, 2 CTAs/SM target.
// CTA = (b,h,128-query tile), 8 warps, cp.async double buffer.
// ---------------------------------------------------------------------------
#define ASTR 36
#define APL (64*ASTR)
#define ASTG (4*APL)

__device__ __forceinline__ void aload(uint32_t sb, int stage, int j0,
                                      const uint32_t* __restrict__ KHg,
                                      const uint32_t* __restrict__ KLg,
                                      const uint32_t* __restrict__ VHg,
                                      const uint32_t* __restrict__ VLg, int tid)
{
    const uint32_t base = sb + (uint32_t)stage * ASTG * 4;
    #pragma unroll
    for (int i = 0; i < 2; i++) {
        int e = tid + i * 256;
        int r = e >> 3, c = e & 7;
        uint32_t o = (uint32_t)(r * ASTR + c * 4) * 4;
        const size_t gk = (size_t)(j0 + r) * 32 + c * 4;
        cp16s(base + o,            KHg + gk);
        cp16s(base + APL*4 + o,    KLg + gk);
        const size_t gv = (size_t)r * 512 + (j0 >> 1) + c * 4;
        cp16s(base + 2*APL*4 + o,  VHg + gv);
        cp16s(base + 3*APL*4 + o,  VLg + gv);
    }
}

__global__ __launch_bounds__(256, 2) void attn_tc(const float* __restrict__ mask,
                                                  float* __restrict__ out)
{
    extern __shared__ uint32_t s[];
    const uint32_t sb = smem_u32(s);

    const int b = blockIdx.z, h = blockIdx.y;
    const int q0 = blockIdx.x * 128;
    const int tid = threadIdx.x, warp = tid >> 5, lane = tid & 31;
    const int g = lane >> 2, tig = lane & 3;
    const int r0 = warp * 16 + g;
    const int mid = lane >> 3, lr = lane & 7;
    const int browl = (mid >> 1) * 8 + lr, bcol = (mid & 1) * 4;   // B-frag ldmatrix offsets

    const size_t bh32 = (size_t)(b * NH + h) * NS * 32;
    const uint32_t* QHg = g_QH + bh32;
    const uint32_t* QLg = g_QL + bh32;
    const uint32_t* KHg = g_KH + bh32;
    const uint32_t* KLg = g_KL + bh32;
    const size_t bhv = (size_t)(b * NH + h) * 64 * 512;
    const uint32_t* VHg = g_VH + bhv;
    const uint32_t* VLg = g_VL + bhv;

    // --- Q bounce through both stages' KH/KL planes, then frags -> registers
    #pragma unroll
    for (int i = 0; i < 4; i++) {
        int e = tid + i * 256;
        int vr = e >> 3, c = e & 7;
        uint32_t idx = (uint32_t)(vr >> 6) * ASTG + (uint32_t)(vr & 63) * ASTR + c * 4;
        *(uint4*)(s + idx)       = *(const uint4*)(QHg + (size_t)(q0 + vr) * 32 + c * 4);
        *(uint4*)(s + idx + APL) = *(const uint4*)(QLg + (size_t)(q0 + vr) * 32 + c * 4);
    }
    __syncthreads();
    uint32_t qh[4][4], ql[4][4];
    {
        const uint32_t qbase = (uint32_t)(r0 >> 6) * ASTG;
        const int lrq = r0 & 63;
        #pragma unroll
        for (int kg = 0; kg < 4; kg++) {
            const int kp1 = kg * 8 + tig, kp2 = kp1 + 4;
            qh[kg][0] = s[qbase + lrq*ASTR + kp1]; qh[kg][1] = s[qbase + (lrq+8)*ASTR + kp1];
            qh[kg][2] = s[qbase + lrq*ASTR + kp2]; qh[kg][3] = s[qbase + (lrq+8)*ASTR + kp2];
            ql[kg][0] = s[qbase + APL + lrq*ASTR + kp1]; ql[kg][1] = s[qbase + APL + (lrq+8)*ASTR + kp1];
            ql[kg][2] = s[qbase + APL + lrq*ASTR + kp2]; ql[kg][3] = s[qbase + APL + (lrq+8)*ASTR + kp2];
        }
    }
    __syncthreads();

    float o[8][4];
    #pragma unroll
    for (int nt = 0; nt < 8; nt++)
        #pragma unroll
        for (int e = 0; e < 4; e++) o[nt][e] = 0.f;
    float mrow[2] = {-3.4e38f, -3.4e38f};
    float lsum[2] = {0.f, 0.f};

    aload(sb, 0, 0, KHg, KLg, VHg, VLg, tid);
    CP_COMMIT();

    for (int jt = 0; jt < NS/64; jt++) {
        if (jt + 1 < NS/64)
            aload(sb, (jt + 1) & 1, (jt + 1) * 64, KHg, KLg, VHg, VLg, tid);
        CP_COMMIT();
        CP_WAIT1();
        __syncthreads();

        const uint32_t KHb = sb + ((jt & 1) * ASTG) * 4;
        const uint32_t KLb = KHb + APL * 4;
        const uint32_t VHb = KHb + 2 * APL * 4;
        const uint32_t VLb = KHb + 3 * APL * 4;
        const int j0 = jt * 64;

        // ---- scores S[16x64] per warp, bf16x3, ldmatrix B-frags ----
        float c[8][4];
        #pragma unroll
        for (int nt = 0; nt < 8; nt++)
            #pragma unroll
            for (int e = 0; e < 4; e++) c[nt][e] = 0.f;

        #pragma unroll
        for (int kg = 0; kg < 4; kg++) {
            const int kgb = kg * 8;
            #pragma unroll
            for (int np = 0; np < 4; np++) {
                const int nt0 = 2 * np;
                const uint32_t ob = (uint32_t)((nt0*8 + browl) * ASTR + kgb + bcol) * 4;
                uint32_t kh[4], kl[4];
                ldsm4(kh, KHb + ob);
                ldsm4(kl, KLb + ob);
                mma16(c[nt0],   qh[kg], kl);
                mma16(c[nt0],   ql[kg], kh);
                mma16(c[nt0],   qh[kg], kh);
                mma16(c[nt0+1], qh[kg], kl + 2);
                mma16(c[nt0+1], ql[kg], kh + 2);
                mma16(c[nt0+1], qh[kg], kh + 2);
            }
        }

        // ---- mask ----
        const float* mr = mask + ((size_t)b*NS + (q0 + r0))*NS + j0 + 2*tig;
        #pragma unroll
        for (int nt = 0; nt < 8; nt++) {
            float2 m0v = *(const float2*)(mr + nt*8);
            float2 m1v = *(const float2*)(mr + (size_t)8*NS + nt*8);
            c[nt][0] = fmaf(m0v.x - 1.f, 1e6f, c[nt][0]);
            c[nt][1] = fmaf(m0v.y - 1.f, 1e6f, c[nt][1]);
            c[nt][2] = fmaf(m1v.x - 1.f, 1e6f, c[nt][2]);
            c[nt][3] = fmaf(m1v.y - 1.f, 1e6f, c[nt][3]);
        }

        // ---- online softmax ----
        #pragma unroll
        for (int sl = 0; sl < 2; sl++) {
            float cm = -3.4e38f;
            #pragma unroll
            for (int nt = 0; nt < 8; nt++)
                cm = fmaxf(cm, fmaxf(c[nt][2*sl], c[nt][2*sl + 1]));
            cm = fmaxf(cm, __shfl_xor_sync(0xffffffffu, cm, 1));
            cm = fmaxf(cm, __shfl_xor_sync(0xffffffffu, cm, 2));
            const float mn = fmaxf(mrow[sl], cm);
            const float alc = __expf(mrow[sl] - mn);
            mrow[sl] = mn;
            float rs = 0.f;
            #pragma unroll
            for (int nt = 0; nt < 8; nt++) {
                c[nt][2*sl]     = __expf(c[nt][2*sl]     - mn);
                c[nt][2*sl + 1] = __expf(c[nt][2*sl + 1] - mn);
                rs += c[nt][2*sl] + c[nt][2*sl + 1];
            }
            rs += __shfl_xor_sync(0xffffffffu, rs, 1);
            rs += __shfl_xor_sync(0xffffffffu, rs, 2);
            lsum[sl] = lsum[sl] * alc + rs;
            #pragma unroll
            for (int nt = 0; nt < 8; nt++) {
                o[nt][2*sl]     *= alc;
                o[nt][2*sl + 1] *= alc;
            }
        }

        // ---- O += P @ V, ldmatrix V-frags ----
        #pragma unroll
        for (int q = 0; q < 4; q++) {
            uint32_t ph[4], pl[4];
            split2(c[2*q    ][0], c[2*q    ][1], ph[0], pl[0]);
            split2(c[2*q    ][2], c[2*q    ][3], ph[1], pl[1]);
            split2(c[2*q + 1][0], c[2*q + 1][1], ph[2], pl[2]);
            split2(c[2*q + 1][2], c[2*q + 1][3], ph[3], pl[3]);
            const int jb = q * 8;
            #pragma unroll
            for (int np = 0; np < 4; np++) {
                const int nt0 = 2 * np;
                const uint32_t ob = (uint32_t)((nt0*8 + browl) * ASTR + jb + bcol) * 4;
                uint32_t vh[4], vl[4];
                ldsm4(vh, VHb + ob);
                ldsm4(vl, VLb + ob);
                mma16(o[nt0],   ph, vl);
                mma16(o[nt0],   pl, vh);
                mma16(o[nt0],   ph, vh);
                mma16(o[nt0+1], ph, vl + 2);
                mma16(o[nt0+1], pl, vh + 2);
                mma16(o[nt0+1], ph, vh + 2);
            }
        }
        __syncthreads();
    }

    // ---- epilogue ----
    const float inv0 = 1.0f / lsum[0];
    const float inv1 = 1.0f / lsum[1];
    float* orow = out + ((size_t)b*NS + (q0 + r0))*NE + h*ND + 2*tig;
    #pragma unroll
    for (int nt = 0; nt < 8; nt++) {
        *(float2*)(orow + nt*8) = make_float2(o[nt][0]*inv0, o[nt][1]*inv0);
        *(float2*)(orow + (size_t)8*NE + nt*8) = make_float2(o[nt][2]*inv1, o[nt][3]*inv1);
    }
}

extern "C" void kernel_launch(void* const* d_in, const int* in_sizes, int n_in,
                              void* d_out, int out_size)
{
    const float* query = (const float*)d_in[0];
    const float* key   = (const float*)d_in[1];
    const float* value = (const float*)d_in[2];
    const float* mask  = (const float*)d_in[3];
    const float* Wq    = (const float*)d_in[4];
    const float* bq    = (const float*)d_in[5];
    const float* Wk    = (const float*)d_in[6];
    const float* bk    = (const float*)d_in[7];
    const float* Wv    = (const float*)d_in[8];
    const float* bv    = (const float*)d_in[9];
    float* out = (float*)d_out;

    split_in<<<dim3(512, 6), 256>>>(query, key, value, Wq, Wk, Wv);

    const int proj_smem = 2 * PSTG * 4;   // 81920 B
    cudaFuncSetAttribute(proj_tc, cudaFuncAttributeMaxDynamicSharedMemorySize, proj_smem);
    dim3 pg(NE / 128, (NB * NS) / 128, 3);
    proj_tc<<<pg, 256, proj_smem>>>(bq, bk, bv);

    const int attn_smem = 2 * ASTG * 4;   // 73728 B
    cudaFuncSetAttribute(attn_tc, cudaFuncAttributeMaxDynamicSharedMemorySize, attn_smem);
    dim3 ag(NS/128, NH, NB);
    attn_tc<<<ag, 256, attn_smem>>>(mask, out);
}

// round 11
// speedup vs baseline: 2.6064x; 1.0960x over previous
#include <cuda_runtime.h>
#include <cstdint>
#include <math.h>

#define NB 4
#define NH 16
#define NS 1024
#define ND 64
#define NE 1024

// ---------------------------------------------------------------------------
// Global scratch: bf16 hi/lo packed planes (u32 = 2 bf16, consecutive k).
// ---------------------------------------------------------------------------
__device__ uint32_t g_XH[3 * 4096 * 512];   // inputs  [z][m][kp]
__device__ uint32_t g_XL[3 * 4096 * 512];
__device__ uint32_t g_WH[3 * 1024 * 512];   // weights [z][n][kp]
__device__ uint32_t g_WL[3 * 1024 * 512];
__device__ uint32_t g_QH[NB*NH*NS*32];      // Q/K: [(b,h)][s][dp]
__device__ uint32_t g_QL[NB*NH*NS*32];
__device__ uint32_t g_KH[NB*NH*NS*32];
__device__ uint32_t g_KL[NB*NH*NS*32];
__device__ uint32_t g_VH[NB*NH*64*512];     // V: [(b,h)][d][sp]  (key-pair packed)
__device__ uint32_t g_VL[NB*NH*64*512];

// ---------------------------------------------------------------------------
// helpers
// ---------------------------------------------------------------------------
__device__ __forceinline__ uint32_t smem_u32(const void* p) {
    uint32_t a;
    asm("{ .reg .u64 t; cvta.to.shared.u64 t, %1; cvt.u32.u64 %0, t; }" : "=r"(a) : "l"(p));
    return a;
}
__device__ __forceinline__ void cp16s(uint32_t dst, const void* src) {
    asm volatile("cp.async.cg.shared.global [%0], [%1], 16;" :: "r"(dst), "l"(src));
}
#define CP_COMMIT() asm volatile("cp.async.commit_group;" ::: "memory")
#define CP_WAIT1()  asm volatile("cp.async.wait_group 1;"  ::: "memory")

__device__ __forceinline__ uint32_t packbf(float e0, float e1) {
    uint32_t r; asm("cvt.rn.bf16x2.f32 %0, %1, %2;" : "=r"(r) : "f"(e1), "f"(e0)); return r;
}
__device__ __forceinline__ void split2(float x0, float x1, uint32_t& h, uint32_t& l) {
    h = packbf(x0, x1);
    float h0 = __uint_as_float(h << 16);
    float h1 = __uint_as_float(h & 0xffff0000u);
    l = packbf(x0 - h0, x1 - h1);
}

// bf16 m16n8k16 mma.sync
__device__ __forceinline__ void mma16(float* d, const uint32_t* a, const uint32_t* b) {
    asm volatile(
        "mma.sync.aligned.m16n8k16.row.col.f32.bf16.bf16.f32 "
        "{%0,%1,%2,%3}, {%4,%5,%6,%7}, {%8,%9}, {%0,%1,%2,%3};"
        : "+f"(d[0]), "+f"(d[1]), "+f"(d[2]), "+f"(d[3])
        : "r"(a[0]), "r"(a[1]), "r"(a[2]), "r"(a[3]), "r"(b[0]), "r"(b[1]));
}

// ldmatrix x4
__device__ __forceinline__ void ldsm4(uint32_t* r, uint32_t addr) {
    asm volatile("ldmatrix.sync.aligned.m8n8.x4.shared.b16 {%0,%1,%2,%3}, [%4];"
        : "=r"(r[0]), "=r"(r[1]), "=r"(r[2]), "=r"(r[3]) : "r"(addr));
}

// ---------------------------------------------------------------------------
// Pre-pass: split 6 fp32 tensors into bf16 hi/lo packed planes.
// ---------------------------------------------------------------------------
__global__ void split_in(const float* __restrict__ q, const float* __restrict__ k,
                         const float* __restrict__ v, const float* __restrict__ wq,
                         const float* __restrict__ wk, const float* __restrict__ wv)
{
    const int z = blockIdx.y;
    const float* src; uint32_t* H; uint32_t* L; int n;
    if (z < 3) {
        src = (z == 0) ? q : (z == 1) ? k : v;
        H = g_XH + (size_t)z * 4096 * 512; L = g_XL + (size_t)z * 4096 * 512;
        n = 4096 * 512;
    } else {
        src = (z == 3) ? wq : (z == 4) ? wk : wv;
        H = g_WH + (size_t)(z - 3) * 1024 * 512; L = g_WL + (size_t)(z - 3) * 1024 * 512;
        n = 1024 * 512;
    }
    for (int i = blockIdx.x * blockDim.x + threadIdx.x; i < n; i += gridDim.x * blockDim.x) {
        float2 x = ((const float2*)src)[i];
        uint32_t h, l; split2(x.x, x.y, h, l);
        H[i] = h; L[i] = l;
    }
}

// ---------------------------------------------------------------------------
// bf16x3 projection (unchanged from R9, validated).
// ---------------------------------------------------------------------------
#define PSTR 20
#define PLSZ (128*PSTR)
#define PSTG (4*PLSZ)
#define PNIT 32

__device__ __forceinline__ void pstage(uint32_t sbase, const uint32_t* __restrict__ XH,
                                       const uint32_t* __restrict__ XL,
                                       const uint32_t* __restrict__ WH,
                                       const uint32_t* __restrict__ WL,
                                       int m0, int n0, int it, int tid)
{
    #pragma unroll
    for (int i = 0; i < 2; i++) {
        int e = tid + i * 256;
        int r = e >> 2, c = e & 3;
        uint32_t o = (uint32_t)(r * PSTR + c * 4) * 4;
        const size_t gi = (size_t)(m0 + r) * 512 + it * 16 + c * 4;
        cp16s(sbase + o,              XH + gi);
        cp16s(sbase + PLSZ*4 + o,     XL + gi);
        const size_t gw = (size_t)(n0 + r) * 512 + it * 16 + c * 4;
        cp16s(sbase + 2*PLSZ*4 + o,   WH + gw);
        cp16s(sbase + 3*PLSZ*4 + o,   WL + gw);
    }
}

__global__ __launch_bounds__(256, 2) void proj_tc(
    const float* __restrict__ Bq, const float* __restrict__ Bk, const float* __restrict__ Bv)
{
    extern __shared__ uint32_t sm[];
    const uint32_t sb = smem_u32(sm);

    const int tid = threadIdx.x;
    const int z = blockIdx.z;
    const uint32_t* XH = g_XH + (size_t)z * 4096 * 512;
    const uint32_t* XL = g_XL + (size_t)z * 4096 * 512;
    const uint32_t* WH = g_WH + (size_t)z * 1024 * 512;
    const uint32_t* WL = g_WL + (size_t)z * 1024 * 512;
    const float* Bi = (z == 0) ? Bq : (z == 1) ? Bk : Bv;
    const float scale = (z == 0) ? 0.125f : 1.0f;

    const int m0 = blockIdx.y * 128;
    const int n0 = blockIdx.x * 128;

    const int warp = tid >> 5, lane = tid & 31;
    const int g = lane >> 2, tig = lane & 3;
    const int wm = warp >> 1, wn = warp & 1;
    const int mid = lane >> 3, lr = lane & 7;
    const int arowl = (mid & 1) * 8 + lr, acol = (mid >> 1) * 4;
    const int browl = (mid >> 1) * 8 + lr, bcol = (mid & 1) * 4;

    float cfr[2][8][4];
    #pragma unroll
    for (int mt = 0; mt < 2; mt++)
        #pragma unroll
        for (int nt = 0; nt < 8; nt++)
            #pragma unroll
            for (int e = 0; e < 4; e++) cfr[mt][nt][e] = 0.f;

    pstage(sb, XH, XL, WH, WL, m0, n0, 0, tid);
    CP_COMMIT();

    for (int it = 0; it < PNIT; it++) {
        if (it + 1 < PNIT)
            pstage(sb + ((it + 1) & 1) * PSTG * 4, XH, XL, WH, WL, m0, n0, it + 1, tid);
        CP_COMMIT();
        CP_WAIT1();
        __syncthreads();

        const uint32_t AHb = sb + ((it & 1) * PSTG) * 4;
        const uint32_t ALb = AHb + PLSZ * 4;
        const uint32_t BHb = AHb + 2 * PLSZ * 4;
        const uint32_t BLb = AHb + 3 * PLSZ * 4;

        #pragma unroll
        for (int kg = 0; kg < 2; kg++) {
            const int kgb = kg * 8;
            uint32_t ah[2][4], al[2][4];
            #pragma unroll
            for (int mt = 0; mt < 2; mt++) {
                const uint32_t oa = (uint32_t)((wm*32 + mt*16 + arowl) * PSTR + kgb + acol) * 4;
                ldsm4(ah[mt], AHb + oa);
                ldsm4(al[mt], ALb + oa);
            }
            #pragma unroll
            for (int np = 0; np < 4; np++) {
                const int nt0 = 2 * np;
                const uint32_t ob = (uint32_t)((wn*64 + nt0*8 + browl) * PSTR + kgb + bcol) * 4;
                uint32_t bh[4], bl[4];
                ldsm4(bh, BHb + ob);
                ldsm4(bl, BLb + ob);
                #pragma unroll
                for (int mt = 0; mt < 2; mt++) {
                    mma16(cfr[mt][nt0],   ah[mt], bl);
                    mma16(cfr[mt][nt0],   al[mt], bh);
                    mma16(cfr[mt][nt0],   ah[mt], bh);
                    mma16(cfr[mt][nt0+1], ah[mt], bl + 2);
                    mma16(cfr[mt][nt0+1], al[mt], bh + 2);
                    mma16(cfr[mt][nt0+1], ah[mt], bh + 2);
                }
            }
        }
        __syncthreads();
    }

    float* Cs = (float*)sm;
    #pragma unroll
    for (int mt = 0; mt < 2; mt++) {
        const int rm = wm * 32 + mt * 16 + g;
        #pragma unroll
        for (int nt = 0; nt < 8; nt++) {
            const int cn = wn * 64 + nt * 8 + 2 * tig;
            Cs[(rm    ) * 132 + cn    ] = cfr[mt][nt][0];
            Cs[(rm    ) * 132 + cn + 1] = cfr[mt][nt][1];
            Cs[(rm + 8) * 132 + cn    ] = cfr[mt][nt][2];
            Cs[(rm + 8) * 132 + cn + 1] = cfr[mt][nt][3];
        }
    }
    __syncthreads();

    if (z < 2) {
        uint32_t* OH = (z == 0) ? g_QH : g_KH;
        uint32_t* OL = (z == 0) ? g_QL : g_KL;
        const int qcol = (tid & 15) * 4;
        #pragma unroll
        for (int hh = 0; hh < 2; hh++) {
            const int h = ((n0 + hh * 64) >> 6);
            const float4 bv = *(const float4*)(Bi + n0 + hh * 64 + qcol);
            #pragma unroll
            for (int p = 0; p < 8; p++) {
                const int idx = tid + p * 256;
                const int m = idx >> 4;
                const int gm = m0 + m, b = gm >> 10, s = gm & (NS - 1);
                const float* src = Cs + m * 132 + hh * 64 + qcol;
                float v0 = (src[0] + bv.x) * scale;
                float v1 = (src[1] + bv.y) * scale;
                float v2 = (src[2] + bv.z) * scale;
                float v3 = (src[3] + bv.w) * scale;
                uint32_t h0, l0, h1, l1;
                split2(v0, v1, h0, l0);
                split2(v2, v3, h1, l1);
                const size_t o = ((size_t)(b * NH + h) * NS + s) * 32 + (qcol >> 1);
                *(uint2*)(OH + o) = make_uint2(h0, h1);
                *(uint2*)(OL + o) = make_uint2(l0, l1);
            }
        }
    } else {
        #pragma unroll 1
        for (int p = 0; p < 32; p++) {
            const int e = tid + p * 256;
            const int sp = e & 63;
            const int dl = e >> 6;
            const int n = n0 + dl;
            const int h = n >> 6, dd = n & 63;
            const int gm = m0 + 2 * sp;
            const int b = gm >> 10;
            const int spg = (gm & (NS - 1)) >> 1;
            const float bi = Bi[n];
            float v0 = Cs[(2*sp    ) * 132 + dl] + bi;
            float v1 = Cs[(2*sp + 1) * 132 + dl] + bi;
            uint32_t hh, ll;
            split2(v0, v1, hh, ll);
            const size_t o = ((size_t)(b * NH + h) * 64 + dd) * 512 + spg;
            g_VH[o] = hh;
            g_VL[o] = ll;
        }
    }
}

// ---------------------------------------------------------------------------
// bf16x3 flash attention, v4 (race-fixed): 3-stage cp.async ring, ONE barrier
// per tile. Order: wait(own copies of stage jt) -> barrier (publishes stage
// jt AND proves all warps finished reading stage (jt-1)%3 == (jt+2)%3) ->
// prefetch stage (jt+2)%3 -> compute stage jt%3. 8 warps, 2 CTAs/SM.
// ---------------------------------------------------------------------------
#define ASTR 36
#define APL (64*ASTR)
#define ASTG (4*APL)
#define NSTAGE 3

__device__ __forceinline__ void aload(uint32_t sb, int stage, int j0,
                                      const uint32_t* __restrict__ KHg,
                                      const uint32_t* __restrict__ KLg,
                                      const uint32_t* __restrict__ VHg,
                                      const uint32_t* __restrict__ VLg, int tid)
{
    const uint32_t base = sb + (uint32_t)stage * ASTG * 4;
    #pragma unroll
    for (int i = 0; i < 2; i++) {
        int e = tid + i * 256;
        int r = e >> 3, c = e & 7;
        uint32_t o = (uint32_t)(r * ASTR + c * 4) * 4;
        const size_t gk = (size_t)(j0 + r) * 32 + c * 4;
        cp16s(base + o,            KHg + gk);
        cp16s(base + APL*4 + o,    KLg + gk);
        const size_t gv = (size_t)r * 512 + (j0 >> 1) + c * 4;
        cp16s(base + 2*APL*4 + o,  VHg + gv);
        cp16s(base + 3*APL*4 + o,  VLg + gv);
    }
}

__global__ __launch_bounds__(256, 2) void attn_tc(const float* __restrict__ mask,
                                                  float* __restrict__ out)
{
    extern __shared__ uint32_t s[];
    const uint32_t sb = smem_u32(s);

    const int b = blockIdx.z, h = blockIdx.y;
    const int q0 = blockIdx.x * 128;
    const int tid = threadIdx.x, warp = tid >> 5, lane = tid & 31;
    const int g = lane >> 2, tig = lane & 3;
    const int r0 = warp * 16 + g;
    const int mid = lane >> 3, lr = lane & 7;
    const int browl = (mid >> 1) * 8 + lr, bcol = (mid & 1) * 4;

    const size_t bh32 = (size_t)(b * NH + h) * NS * 32;
    const uint32_t* QHg = g_QH + bh32;
    const uint32_t* QLg = g_QL + bh32;
    const uint32_t* KHg = g_KH + bh32;
    const uint32_t* KLg = g_KL + bh32;
    const size_t bhv = (size_t)(b * NH + h) * 64 * 512;
    const uint32_t* VHg = g_VH + bhv;
    const uint32_t* VLg = g_VL + bhv;

    // --- Q bounce through stage0/1 KH/KL planes, then frags -> registers ---
    #pragma unroll
    for (int i = 0; i < 4; i++) {
        int e = tid + i * 256;
        int vr = e >> 3, c = e & 7;
        uint32_t idx = (uint32_t)(vr >> 6) * ASTG + (uint32_t)(vr & 63) * ASTR + c * 4;
        *(uint4*)(s + idx)       = *(const uint4*)(QHg + (size_t)(q0 + vr) * 32 + c * 4);
        *(uint4*)(s + idx + APL) = *(const uint4*)(QLg + (size_t)(q0 + vr) * 32 + c * 4);
    }
    __syncthreads();
    uint32_t qh[4][4], ql[4][4];
    {
        const uint32_t qbase = (uint32_t)(r0 >> 6) * ASTG;
        const int lrq = r0 & 63;
        #pragma unroll
        for (int kg = 0; kg < 4; kg++) {
            const int kp1 = kg * 8 + tig, kp2 = kp1 + 4;
            qh[kg][0] = s[qbase + lrq*ASTR + kp1]; qh[kg][1] = s[qbase + (lrq+8)*ASTR + kp1];
            qh[kg][2] = s[qbase + lrq*ASTR + kp2]; qh[kg][3] = s[qbase + (lrq+8)*ASTR + kp2];
            ql[kg][0] = s[qbase + APL + lrq*ASTR + kp1]; ql[kg][1] = s[qbase + APL + (lrq+8)*ASTR + kp1];
            ql[kg][2] = s[qbase + APL + lrq*ASTR + kp2]; ql[kg][3] = s[qbase + APL + (lrq+8)*ASTR + kp2];
        }
    }
    __syncthreads();

    float o[8][4];
    #pragma unroll
    for (int nt = 0; nt < 8; nt++)
        #pragma unroll
        for (int e = 0; e < 4; e++) o[nt][e] = 0.f;
    float mrow[2] = {-3.4e38f, -3.4e38f};
    float lsum[2] = {0.f, 0.f};

    aload(sb, 0, 0, KHg, KLg, VHg, VLg, tid);
    CP_COMMIT();
    aload(sb, 1, 64, KHg, KLg, VHg, VLg, tid);
    CP_COMMIT();

    for (int jt = 0; jt < NS/64; jt++) {
        CP_WAIT1();            // own copies of stage jt%3 have landed
        __syncthreads();       // publishes stage jt; proves stage (jt+2)%3 free
        if (jt + 2 < NS/64)
            aload(sb, (jt + 2) % NSTAGE, (jt + 2) * 64, KHg, KLg, VHg, VLg, tid);
        CP_COMMIT();           // unconditional: uniform group counts

        const uint32_t KHb = sb + ((jt % NSTAGE) * ASTG) * 4;
        const uint32_t KLb = KHb + APL * 4;
        const uint32_t VHb = KHb + 2 * APL * 4;
        const uint32_t VLb = KHb + 3 * APL * 4;
        const int j0 = jt * 64;

        // ---- scores S[16x64] per warp, bf16x3, ldmatrix B-frags ----
        float c[8][4];
        #pragma unroll
        for (int nt = 0; nt < 8; nt++)
            #pragma unroll
            for (int e = 0; e < 4; e++) c[nt][e] = 0.f;

        #pragma unroll
        for (int kg = 0; kg < 4; kg++) {
            const int kgb = kg * 8;
            #pragma unroll
            for (int np = 0; np < 4; np++) {
                const int nt0 = 2 * np;
                const uint32_t ob = (uint32_t)((nt0*8 + browl) * ASTR + kgb + bcol) * 4;
                uint32_t kh[4], kl[4];
                ldsm4(kh, KHb + ob);
                ldsm4(kl, KLb + ob);
                mma16(c[nt0],   qh[kg], kl);
                mma16(c[nt0],   ql[kg], kh);
                mma16(c[nt0],   qh[kg], kh);
                mma16(c[nt0+1], qh[kg], kl + 2);
                mma16(c[nt0+1], ql[kg], kh + 2);
                mma16(c[nt0+1], qh[kg], kh + 2);
            }
        }

        // ---- mask ----
        const float* mr = mask + ((size_t)b*NS + (q0 + r0))*NS + j0 + 2*tig;
        #pragma unroll
        for (int nt = 0; nt < 8; nt++) {
            float2 m0v = *(const float2*)(mr + nt*8);
            float2 m1v = *(const float2*)(mr + (size_t)8*NS + nt*8);
            c[nt][0] = fmaf(m0v.x - 1.f, 1e6f, c[nt][0]);
            c[nt][1] = fmaf(m0v.y - 1.f, 1e6f, c[nt][1]);
            c[nt][2] = fmaf(m1v.x - 1.f, 1e6f, c[nt][2]);
            c[nt][3] = fmaf(m1v.y - 1.f, 1e6f, c[nt][3]);
        }

        // ---- online softmax ----
        #pragma unroll
        for (int sl = 0; sl < 2; sl++) {
            float cm = -3.4e38f;
            #pragma unroll
            for (int nt = 0; nt < 8; nt++)
                cm = fmaxf(cm, fmaxf(c[nt][2*sl], c[nt][2*sl + 1]));
            cm = fmaxf(cm, __shfl_xor_sync(0xffffffffu, cm, 1));
            cm = fmaxf(cm, __shfl_xor_sync(0xffffffffu, cm, 2));
            const float mn = fmaxf(mrow[sl], cm);
            const float alc = __expf(mrow[sl] - mn);
            mrow[sl] = mn;
            float rs = 0.f;
            #pragma unroll
            for (int nt = 0; nt < 8; nt++) {
                c[nt][2*sl]     = __expf(c[nt][2*sl]     - mn);
                c[nt][2*sl + 1] = __expf(c[nt][2*sl + 1] - mn);
                rs += c[nt][2*sl] + c[nt][2*sl + 1];
            }
            rs += __shfl_xor_sync(0xffffffffu, rs, 1);
            rs += __shfl_xor_sync(0xffffffffu, rs, 2);
            lsum[sl] = lsum[sl] * alc + rs;
            #pragma unroll
            for (int nt = 0; nt < 8; nt++) {
                o[nt][2*sl]     *= alc;
                o[nt][2*sl + 1] *= alc;
            }
        }

        // ---- O += P @ V, ldmatrix V-frags ----
        #pragma unroll
        for (int q = 0; q < 4; q++) {
            uint32_t ph[4], pl[4];
            split2(c[2*q    ][0], c[2*q    ][1], ph[0], pl[0]);
            split2(c[2*q    ][2], c[2*q    ][3], ph[1], pl[1]);
            split2(c[2*q + 1][0], c[2*q + 1][1], ph[2], pl[2]);
            split2(c[2*q + 1][2], c[2*q + 1][3], ph[3], pl[3]);
            const int jb = q * 8;
            #pragma unroll
            for (int np = 0; np < 4; np++) {
                const int nt0 = 2 * np;
                const uint32_t ob = (uint32_t)((nt0*8 + browl) * ASTR + jb + bcol) * 4;
                uint32_t vh[4], vl[4];
                ldsm4(vh, VHb + ob);
                ldsm4(vl, VLb + ob);
                mma16(o[nt0],   ph, vl);
                mma16(o[nt0],   pl, vh);
                mma16(o[nt0],   ph, vh);
                mma16(o[nt0+1], ph, vl + 2);
                mma16(o[nt0+1], pl, vh + 2);
                mma16(o[nt0+1], ph, vh + 2);
            }
        }
        // no trailing barrier: next iteration's leading barrier + 3-stage ring
    }

    // ---- epilogue ----
    const float inv0 = 1.0f / lsum[0];
    const float inv1 = 1.0f / lsum[1];
    float* orow = out + ((size_t)b*NS + (q0 + r0))*NE + h*ND + 2*tig;
    #pragma unroll
    for (int nt = 0; nt < 8; nt++) {
        *(float2*)(orow + nt*8) = make_float2(o[nt][0]*inv0, o[nt][1]*inv0);
        *(float2*)(orow + (size_t)8*NE + nt*8) = make_float2(o[nt][2]*inv1, o[nt][3]*inv1);
    }
}

extern "C" void kernel_launch(void* const* d_in, const int* in_sizes, int n_in,
                              void* d_out, int out_size)
{
    const float* query = (const float*)d_in[0];
    const float* key   = (const float*)d_in[1];
    const float* value = (const float*)d_in[2];
    const float* mask  = (const float*)d_in[3];
    const float* Wq    = (const float*)d_in[4];
    const float* bq    = (const float*)d_in[5];
    const float* Wk    = (const float*)d_in[6];
    const float* bk    = (const float*)d_in[7];
    const float* Wv    = (const float*)d_in[8];
    const float* bv    = (const float*)d_in[9];
    float* out = (float*)d_out;

    split_in<<<dim3(512, 6), 256>>>(query, key, value, Wq, Wk, Wv);

    const int proj_smem = 2 * PSTG * 4;   // 81920 B
    cudaFuncSetAttribute(proj_tc, cudaFuncAttributeMaxDynamicSharedMemorySize, proj_smem);
    dim3 pg(NE / 128, (NB * NS) / 128, 3);
    proj_tc<<<pg, 256, proj_smem>>>(bq, bk, bv);

    const int attn_smem = NSTAGE * ASTG * 4;   // 110592 B
    cudaFuncSetAttribute(attn_tc, cudaFuncAttributeMaxDynamicSharedMemorySize, attn_smem);
    dim3 ag(NS/128, NH, NB);
    attn_tc<<<ag, 256, attn_smem>>>(mask, out);
}